// round 1
// baseline (speedup 1.0000x reference)
#include <cuda_runtime.h>
#include <cuda_bf16.h>
#include <cstdint>
#include <cstddef>

// ---------------- problem constants ----------------
#define B_   256
#define T_   361
#define C_   512
#define H_   8
#define DH_  64
#define MLP_ 2048
#define M_   (B_ * T_)          // 92416 rows, divisible by 64
#define SPAN_ 37
#define TABLE_ 1369

// ---------------- scratch (static device globals; no allocation) ----------------
__device__ float g_Y  [(size_t)M_ * C_];     // LN output (reused for LN1 and LN2)
__device__ float g_Q  [(size_t)M_ * C_];
__device__ float g_K  [(size_t)M_ * C_];
__device__ float g_V  [(size_t)M_ * C_];
__device__ float g_CTX[(size_t)M_ * C_];
__device__ float g_X1 [(size_t)M_ * C_];     // x + attn_out (residual for MLP)
__device__ float g_HID[(size_t)M_ * MLP_];
__device__ float g_BIAS[(size_t)H_ * T_ * T_]; // expanded rel-pos bias, 4.2 MB (L2-resident)

// ---------------- LayerNorm: one block (128 thr) per 512-elem row ----------------
__global__ __launch_bounds__(128) void ln_kernel(
    const float* __restrict__ x, const float* __restrict__ g,
    const float* __restrict__ b, float* __restrict__ y) {
  size_t row = blockIdx.x;
  const float4* xr = (const float4*)(x + row * C_);
  float4 v = xr[threadIdx.x];
  float s  = v.x + v.y + v.z + v.w;
  float s2 = fmaf(v.x, v.x, fmaf(v.y, v.y, fmaf(v.z, v.z, v.w * v.w)));
  #pragma unroll
  for (int o = 16; o; o >>= 1) {
    s  += __shfl_xor_sync(0xffffffffu, s, o);
    s2 += __shfl_xor_sync(0xffffffffu, s2, o);
  }
  __shared__ float sh[8];
  int w = threadIdx.x >> 5, ln = threadIdx.x & 31;
  if (ln == 0) { sh[w] = s; sh[4 + w] = s2; }
  __syncthreads();
  s  = sh[0] + sh[1] + sh[2] + sh[3];
  s2 = sh[4] + sh[5] + sh[6] + sh[7];
  float mu  = s * (1.0f / C_);
  float var = s2 * (1.0f / C_) - mu * mu;
  float rs  = rsqrtf(var + 1e-6f);
  float4 gg = ((const float4*)g)[threadIdx.x];
  float4 bb = ((const float4*)b)[threadIdx.x];
  float4 o;
  o.x = (v.x - mu) * rs * gg.x + bb.x;
  o.y = (v.y - mu) * rs * gg.y + bb.y;
  o.z = (v.z - mu) * rs * gg.z + bb.z;
  o.w = (v.w - mu) * rs * gg.w + bb.w;
  ((float4*)(y + row * C_))[threadIdx.x] = o;
}

// ---------------- rel-pos bias expansion: bias[h][t][s] ----------------
__global__ void bias_expand(const float* __restrict__ rpb, float* __restrict__ bias) {
  int h = blockIdx.x / T_, t = blockIdx.x % T_;
  int tr = t / 19, tc = t % 19;
  const float* rh = rpb + h * TABLE_;
  float* br = bias + ((size_t)h * T_ + t) * T_;
  for (int s = threadIdx.x; s < T_; s += blockDim.x) {
    int sr = s / 19, sc = s % 19;
    int idx = (tr - sr + 18) * SPAN_ + (tc - sc + 18);
    br[s] = rh[idx];
  }
}

// ---------------- GEMM: C = epi(A[M,K] @ B[K,N] + bias [+res]) ----------------
// 64x64 block, BK=16, 256 threads, 4x4 micro-tile. M,N,K all multiples of 64/16.
#define GPAD 68
__device__ __forceinline__ float gelu_f(float x) {
  float x3 = x * x * x;
  float t = tanhf(0.7978845608028654f * fmaf(0.044715f, x3, x));
  return 0.5f * x * (1.0f + t);
}

template<int EPI>  // 0: +bias   1: +bias+res   2: gelu(+bias)
__global__ __launch_bounds__(256) void gemm_kernel(
    const float* __restrict__ A, const float* __restrict__ Bm,
    const float* __restrict__ bias, const float* __restrict__ res,
    float* __restrict__ C, int M, int N, int K) {
  __shared__ float As[16 * GPAD];
  __shared__ float Bs[16 * GPAD];
  int tid = threadIdx.x;
  int ty = tid >> 4, tx = tid & 15;
  int row0 = blockIdx.y * 64;
  int col0 = blockIdx.x * 64;
  int arow = tid >> 2, ac4 = (tid & 3) * 4;
  int brow = tid >> 4, bc4 = (tid & 15) * 4;
  const float* Ag = A  + (size_t)(row0 + arow) * K + ac4;
  const float* Bg = Bm + (size_t)brow * N + col0 + bc4;
  float acc[4][4] = {};
  for (int k0 = 0; k0 < K; k0 += 16) {
    float4 av = *(const float4*)(Ag + k0);
    float4 bv = *(const float4*)(Bg + (size_t)k0 * N);
    __syncthreads();
    As[(ac4 + 0) * GPAD + arow] = av.x;
    As[(ac4 + 1) * GPAD + arow] = av.y;
    As[(ac4 + 2) * GPAD + arow] = av.z;
    As[(ac4 + 3) * GPAD + arow] = av.w;
    *(float4*)(Bs + brow * GPAD + bc4) = bv;
    __syncthreads();
    #pragma unroll
    for (int k = 0; k < 16; k++) {
      float4 a = *(const float4*)(As + k * GPAD + ty * 4);
      float4 b = *(const float4*)(Bs + k * GPAD + tx * 4);
      acc[0][0] = fmaf(a.x, b.x, acc[0][0]); acc[0][1] = fmaf(a.x, b.y, acc[0][1]);
      acc[0][2] = fmaf(a.x, b.z, acc[0][2]); acc[0][3] = fmaf(a.x, b.w, acc[0][3]);
      acc[1][0] = fmaf(a.y, b.x, acc[1][0]); acc[1][1] = fmaf(a.y, b.y, acc[1][1]);
      acc[1][2] = fmaf(a.y, b.z, acc[1][2]); acc[1][3] = fmaf(a.y, b.w, acc[1][3]);
      acc[2][0] = fmaf(a.z, b.x, acc[2][0]); acc[2][1] = fmaf(a.z, b.y, acc[2][1]);
      acc[2][2] = fmaf(a.z, b.z, acc[2][2]); acc[2][3] = fmaf(a.z, b.w, acc[2][3]);
      acc[3][0] = fmaf(a.w, b.x, acc[3][0]); acc[3][1] = fmaf(a.w, b.y, acc[3][1]);
      acc[3][2] = fmaf(a.w, b.z, acc[3][2]); acc[3][3] = fmaf(a.w, b.w, acc[3][3]);
    }
  }
  float4 bb = *(const float4*)(bias + col0 + tx * 4);
  #pragma unroll
  for (int i = 0; i < 4; i++) {
    size_t r = (size_t)(row0 + ty * 4 + i);
    size_t off = r * N + col0 + tx * 4;
    float o0 = acc[i][0] + bb.x, o1 = acc[i][1] + bb.y;
    float o2 = acc[i][2] + bb.z, o3 = acc[i][3] + bb.w;
    if (EPI == 1) {
      float4 rr = *(const float4*)(res + off);
      o0 += rr.x; o1 += rr.y; o2 += rr.z; o3 += rr.w;
    }
    if (EPI == 2) { o0 = gelu_f(o0); o1 = gelu_f(o1); o2 = gelu_f(o2); o3 = gelu_f(o3); }
    *(float4*)(C + off) = make_float4(o0, o1, o2, o3);
  }
}

// ---------------- fused flash attention ----------------
// grid: x = q-chunk (6), y = b*H+h (2048). 256 threads.
// Thread (ty=tid/16, tx=tid%16): S rows ty*4..+3, S cols {tx, tx+16, tx+32, tx+48}
// (strided to keep LDS 2-way max). O/V d-cols blocked: tx*4..+3.
#define APAD 68
#define SMEM_ATTN (4 * 64 * APAD * 4)

__global__ __launch_bounds__(256) void attn_kernel(
    const float* __restrict__ Q, const float* __restrict__ Kk,
    const float* __restrict__ Vv, const float* __restrict__ Bt,
    float* __restrict__ ctx) {
  extern __shared__ float sm[];
  float* Qs = sm;
  float* Ks = sm + 64 * APAD;
  float* Vs = sm + 2 * 64 * APAD;
  float* Ps = sm + 3 * 64 * APAD;
  int bh = blockIdx.y;
  int b = bh >> 3, h = bh & 7;
  int t0 = blockIdx.x * 64;
  int tid = threadIdx.x;
  int ty = tid >> 4, tx = tid & 15;
  const size_t base = ((size_t)b * T_) * C_ + h * DH_;

  // load Q tile (zero-fill rows past T)
  #pragma unroll
  for (int i = 0; i < 4; i++) {
    int lin = tid + i * 256;             // float4 index, 1024 total
    int row = lin >> 4, c4 = lin & 15;
    int t = t0 + row;
    float4 val = make_float4(0.f, 0.f, 0.f, 0.f);
    if (t < T_) val = *(const float4*)(Q + base + (size_t)t * C_ + c4 * 4);
    *(float4*)(Qs + row * APAD + c4 * 4) = val;
  }

  float m_[4], l_[4], O[4][4];
  #pragma unroll
  for (int i = 0; i < 4; i++) {
    m_[i] = -1e30f; l_[i] = 0.f;
    #pragma unroll
    for (int j = 0; j < 4; j++) O[i][j] = 0.f;
  }

  for (int s0 = 0; s0 < T_; s0 += 64) {
    __syncthreads();   // covers Q-store on first iter, P@V reads on later iters
    #pragma unroll
    for (int i = 0; i < 4; i++) {
      int lin = tid + i * 256;
      int row = lin >> 4, c4 = lin & 15;
      int s = s0 + row;
      float4 kv = make_float4(0.f, 0.f, 0.f, 0.f), vv = kv;
      if (s < T_) {
        kv = *(const float4*)(Kk + base + (size_t)s * C_ + c4 * 4);
        vv = *(const float4*)(Vv + base + (size_t)s * C_ + c4 * 4);
      }
      *(float4*)(Ks + row * APAD + c4 * 4) = kv;
      *(float4*)(Vs + row * APAD + c4 * 4) = vv;
    }
    __syncthreads();

    // S = Q K^T  (rows ty*4..+3, cols tx+16j)
    float acc[4][4] = {};
    #pragma unroll
    for (int d4 = 0; d4 < 16; d4++) {
      float4 a[4], kk[4];
      #pragma unroll
      for (int i = 0; i < 4; i++)
        a[i] = *(const float4*)(Qs + (ty * 4 + i) * APAD + d4 * 4);
      #pragma unroll
      for (int j = 0; j < 4; j++)
        kk[j] = *(const float4*)(Ks + (tx + 16 * j) * APAD + d4 * 4);
      #pragma unroll
      for (int i = 0; i < 4; i++)
        #pragma unroll
        for (int j = 0; j < 4; j++)
          acc[i][j] = fmaf(a[i].x, kk[j].x,
                      fmaf(a[i].y, kk[j].y,
                      fmaf(a[i].z, kk[j].z,
                      fmaf(a[i].w, kk[j].w, acc[i][j]))));
    }

    // online softmax update
    #pragma unroll
    for (int i = 0; i < 4; i++) {
      int t = t0 + ty * 4 + i;
      int tcl = (t < T_) ? t : 0;
      const float* brow = Bt + ((size_t)h * T_ + tcl) * T_;
      float sv[4];
      #pragma unroll
      for (int j = 0; j < 4; j++) {
        int s = s0 + tx + 16 * j;
        int scl = (s < T_) ? s : 0;
        bool ok = (t < T_) && (s < T_);
        sv[j] = ok ? fmaf(acc[i][j], 0.125f, brow[scl]) : -1e30f;
      }
      float mc = fmaxf(fmaxf(sv[0], sv[1]), fmaxf(sv[2], sv[3]));
      #pragma unroll
      for (int o = 8; o; o >>= 1) mc = fmaxf(mc, __shfl_xor_sync(0xffffffffu, mc, o));
      float mn = fmaxf(m_[i], mc);
      float alpha = __expf(m_[i] - mn);
      float ls = 0.f;
      #pragma unroll
      for (int j = 0; j < 4; j++) { sv[j] = __expf(sv[j] - mn); ls += sv[j]; }
      #pragma unroll
      for (int o = 8; o; o >>= 1) ls += __shfl_xor_sync(0xffffffffu, ls, o);
      l_[i] = l_[i] * alpha + ls;
      m_[i] = mn;
      #pragma unroll
      for (int j = 0; j < 4; j++) O[i][j] *= alpha;
      #pragma unroll
      for (int j = 0; j < 4; j++) Ps[(ty * 4 + i) * APAD + tx + 16 * j] = sv[j];
    }
    __syncthreads();

    // O += P @ V  (O cols tx*4..+3)
    #pragma unroll
    for (int s4 = 0; s4 < 16; s4++) {
      float4 p[4], v[4];
      #pragma unroll
      for (int i = 0; i < 4; i++)
        p[i] = *(const float4*)(Ps + (ty * 4 + i) * APAD + s4 * 4);
      #pragma unroll
      for (int ss = 0; ss < 4; ss++)
        v[ss] = *(const float4*)(Vs + (s4 * 4 + ss) * APAD + tx * 4);
      #pragma unroll
      for (int i = 0; i < 4; i++) {
        O[i][0] = fmaf(p[i].x, v[0].x, fmaf(p[i].y, v[1].x, fmaf(p[i].z, v[2].x, fmaf(p[i].w, v[3].x, O[i][0]))));
        O[i][1] = fmaf(p[i].x, v[0].y, fmaf(p[i].y, v[1].y, fmaf(p[i].z, v[2].y, fmaf(p[i].w, v[3].y, O[i][1]))));
        O[i][2] = fmaf(p[i].x, v[0].z, fmaf(p[i].y, v[1].z, fmaf(p[i].z, v[2].z, fmaf(p[i].w, v[3].z, O[i][2]))));
        O[i][3] = fmaf(p[i].x, v[0].w, fmaf(p[i].y, v[1].w, fmaf(p[i].z, v[2].w, fmaf(p[i].w, v[3].w, O[i][3]))));
      }
    }
  }

  #pragma unroll
  for (int i = 0; i < 4; i++) {
    int t = t0 + ty * 4 + i;
    if (t < T_) {
      float inv = 1.0f / l_[i];
      float4 o = make_float4(O[i][0] * inv, O[i][1] * inv, O[i][2] * inv, O[i][3] * inv);
      *(float4*)(ctx + base + (size_t)t * C_ + tx * 4) = o;
    }
  }
}

// ---------------- launch ----------------
extern "C" void kernel_launch(void* const* d_in, const int* in_sizes, int n_in,
                              void* d_out, int out_size) {
  const float* x    = (const float*)d_in[0];
  const float* ln1s = (const float*)d_in[1];
  const float* ln1b = (const float*)d_in[2];
  const float* Wq   = (const float*)d_in[3];
  const float* bq   = (const float*)d_in[4];
  const float* Wk   = (const float*)d_in[5];
  const float* bk   = (const float*)d_in[6];
  const float* Wv   = (const float*)d_in[7];
  const float* bv   = (const float*)d_in[8];
  const float* Wo   = (const float*)d_in[9];
  const float* bo   = (const float*)d_in[10];
  const float* rpb  = (const float*)d_in[11];
  const float* ln2s = (const float*)d_in[12];
  const float* ln2b = (const float*)d_in[13];
  const float* W1   = (const float*)d_in[14];
  const float* b1   = (const float*)d_in[15];
  const float* W2   = (const float*)d_in[16];
  const float* b2   = (const float*)d_in[17];
  float* out = (float*)d_out;

  float *gY, *gQ, *gK, *gV, *gCTX, *gX1, *gHID, *gBIAS;
  cudaGetSymbolAddress((void**)&gY,    g_Y);
  cudaGetSymbolAddress((void**)&gQ,    g_Q);
  cudaGetSymbolAddress((void**)&gK,    g_K);
  cudaGetSymbolAddress((void**)&gV,    g_V);
  cudaGetSymbolAddress((void**)&gCTX,  g_CTX);
  cudaGetSymbolAddress((void**)&gX1,   g_X1);
  cudaGetSymbolAddress((void**)&gHID,  g_HID);
  cudaGetSymbolAddress((void**)&gBIAS, g_BIAS);

  cudaFuncSetAttribute((const void*)attn_kernel,
                       cudaFuncAttributeMaxDynamicSharedMemorySize, SMEM_ATTN);

  // 1. LN1
  ln_kernel<<<M_, 128>>>(x, ln1s, ln1b, gY);
  // 2. rel-pos bias table (independent)
  bias_expand<<<H_ * T_, 128>>>(rpb, gBIAS);
  // 3. Q, K, V projections
  dim3 g1(C_ / 64, M_ / 64);
  gemm_kernel<0><<<g1, 256>>>(gY, Wq, bq, nullptr, gQ, M_, C_, C_);
  gemm_kernel<0><<<g1, 256>>>(gY, Wk, bk, nullptr, gK, M_, C_, C_);
  gemm_kernel<0><<<g1, 256>>>(gY, Wv, bv, nullptr, gV, M_, C_, C_);
  // 4. fused attention -> ctx
  dim3 ga((T_ + 63) / 64, B_ * H_);
  attn_kernel<<<ga, 256, SMEM_ATTN>>>(gQ, gK, gV, gBIAS, gCTX);
  // 5. output projection + residual -> X1
  gemm_kernel<1><<<g1, 256>>>(gCTX, Wo, bo, x, gX1, M_, C_, C_);
  // 6. LN2
  ln_kernel<<<M_, 128>>>(gX1, ln2s, ln2b, gY);
  // 7. MLP up + gelu
  dim3 g2(MLP_ / 64, M_ / 64);
  gemm_kernel<2><<<g2, 256>>>(gY, W1, b1, nullptr, gHID, M_, MLP_, C_);
  // 8. MLP down + residual -> out
  gemm_kernel<1><<<g1, 256>>>(gHID, W2, b2, gX1, out, M_, C_, MLP_);
}

// round 3
// speedup vs baseline: 1.2897x; 1.2897x over previous
#include <cuda_runtime.h>
#include <cuda_bf16.h>
#include <cstdint>
#include <cstddef>

// ---------------- problem constants ----------------
#define B_   256
#define T_   361
#define C_   512
#define H_   8
#define DH_  64
#define MLP_ 2048
#define M_   (B_ * T_)          // 92416 rows, divisible by 128
#define SPAN_ 37
#define TABLE_ 1369

// ---------------- f32x2 packed-FMA helpers (SASS FFMA2 path) ----------------
typedef unsigned long long u64;
__device__ __forceinline__ u64 pk2(float a, float b) {
  u64 r; asm("mov.b64 %0,{%1,%2};" : "=l"(r) : "f"(a), "f"(b)); return r;
}
__device__ __forceinline__ void fma2(u64& d, u64 a, u64 b) {
  asm("fma.rn.f32x2 %0, %1, %2, %0;" : "+l"(d) : "l"(a), "l"(b));
}
__device__ __forceinline__ void mul2(u64& d, u64 a) {
  asm("mul.rn.f32x2 %0, %0, %1;" : "+l"(d) : "l"(a));
}
__device__ __forceinline__ float2 up2(u64 v) {
  float2 r; asm("mov.b64 {%0,%1},%2;" : "=f"(r.x), "=f"(r.y) : "l"(v)); return r;
}

// ---------------- scratch (static device globals; no allocation) ----------------
__device__ float g_Y  [(size_t)M_ * C_];
__device__ float g_Q  [(size_t)M_ * C_];
__device__ float g_K  [(size_t)M_ * C_];
__device__ float g_V  [(size_t)M_ * C_];
__device__ float g_CTX[(size_t)M_ * C_];
__device__ float g_X1 [(size_t)M_ * C_];
__device__ float g_HID[(size_t)M_ * MLP_];
__device__ float g_BIAS[(size_t)H_ * T_ * T_];

// ---------------- LayerNorm: one block (128 thr) per 512-elem row ----------------
__global__ __launch_bounds__(128) void ln_kernel(
    const float* __restrict__ x, const float* __restrict__ g,
    const float* __restrict__ b, float* __restrict__ y) {
  size_t row = blockIdx.x;
  const float4* xr = (const float4*)(x + row * C_);
  float4 v = xr[threadIdx.x];
  float s  = v.x + v.y + v.z + v.w;
  float s2 = fmaf(v.x, v.x, fmaf(v.y, v.y, fmaf(v.z, v.z, v.w * v.w)));
  #pragma unroll
  for (int o = 16; o; o >>= 1) {
    s  += __shfl_xor_sync(0xffffffffu, s, o);
    s2 += __shfl_xor_sync(0xffffffffu, s2, o);
  }
  __shared__ float sh[8];
  int w = threadIdx.x >> 5, ln = threadIdx.x & 31;
  if (ln == 0) { sh[w] = s; sh[4 + w] = s2; }
  __syncthreads();
  s  = sh[0] + sh[1] + sh[2] + sh[3];
  s2 = sh[4] + sh[5] + sh[6] + sh[7];
  float mu  = s * (1.0f / C_);
  float var = s2 * (1.0f / C_) - mu * mu;
  float rs  = rsqrtf(var + 1e-6f);
  float4 gg = ((const float4*)g)[threadIdx.x];
  float4 bb = ((const float4*)b)[threadIdx.x];
  float4 o;
  o.x = (v.x - mu) * rs * gg.x + bb.x;
  o.y = (v.y - mu) * rs * gg.y + bb.y;
  o.z = (v.z - mu) * rs * gg.z + bb.z;
  o.w = (v.w - mu) * rs * gg.w + bb.w;
  ((float4*)(y + row * C_))[threadIdx.x] = o;
}

// ---------------- rel-pos bias expansion: bias[h][t][s] ----------------
__global__ void bias_expand(const float* __restrict__ rpb, float* __restrict__ bias) {
  int h = blockIdx.x / T_, t = blockIdx.x % T_;
  int tr = t / 19, tc = t % 19;
  const float* rh = rpb + h * TABLE_;
  float* br = bias + ((size_t)h * T_ + t) * T_;
  for (int s = threadIdx.x; s < T_; s += blockDim.x) {
    int sr = s / 19, sc = s % 19;
    int idx = (tr - sr + 18) * SPAN_ + (tc - sc + 18);
    br[s] = rh[idx];
  }
}

__device__ __forceinline__ float gelu_f(float x) {
  float x3 = x * x * x;
  float t = tanhf(0.7978845608028654f * fmaf(0.044715f, x3, x));
  return 0.5f * x * (1.0f + t);
}

// ---------------- GEMM v2: 128x128 block, BK=16, 256 thr, 8x8 micro, FFMA2 ----------------
// C = epi(A[M,K] @ B[K,N] + bias [+res]);  M%128==0, N%128==0, K%16==0
#define GLD 132   // smem row stride (floats), 16B-aligned, kills 4-way conflicts
template<int EPI>  // 0: +bias   1: +bias+res   2: gelu(+bias)
__global__ __launch_bounds__(256, 2) void gemm_kernel(
    const float* __restrict__ A, const float* __restrict__ Bm,
    const float* __restrict__ bias, const float* __restrict__ res,
    float* __restrict__ C, int M, int N, int K) {
  __shared__ float As[16 * GLD];   // As[k][m] transposed
  __shared__ float Bs[16 * GLD];   // Bs[k][n]
  int tid = threadIdx.x;
  int ty = tid >> 4, tx = tid & 15;
  size_t row0 = (size_t)blockIdx.y * 128;
  int col0 = blockIdx.x * 128;

  int arow = tid >> 2, ak4 = (tid & 3) * 4;     // A tile: 128 rows x 16 k
  int bkr  = tid >> 5, bn4 = (tid & 31) * 4;    // B tile: 16 k x 128 n
  const float* Ag = A  + (row0 + arow) * (size_t)K + ak4;
  const float* Bg = Bm + (size_t)bkr * N + col0 + bn4;
  const size_t a64 = 64 * (size_t)K;
  const size_t b8  = 8 * (size_t)N;

  u64 acc[8][4] = {};

  float4 pa0 = *(const float4*)Ag;
  float4 pa1 = *(const float4*)(Ag + a64);
  float4 pb0 = *(const float4*)Bg;
  float4 pb1 = *(const float4*)(Bg + b8);
  As[(ak4 + 0) * GLD + arow] = pa0.x; As[(ak4 + 1) * GLD + arow] = pa0.y;
  As[(ak4 + 2) * GLD + arow] = pa0.z; As[(ak4 + 3) * GLD + arow] = pa0.w;
  As[(ak4 + 0) * GLD + arow + 64] = pa1.x; As[(ak4 + 1) * GLD + arow + 64] = pa1.y;
  As[(ak4 + 2) * GLD + arow + 64] = pa1.z; As[(ak4 + 3) * GLD + arow + 64] = pa1.w;
  *(float4*)(Bs + bkr * GLD + bn4) = pb0;
  *(float4*)(Bs + (bkr + 8) * GLD + bn4) = pb1;
  __syncthreads();

  for (int k0 = 16; k0 <= K; k0 += 16) {
    bool more = (k0 < K);
    if (more) {
      pa0 = *(const float4*)(Ag + k0);
      pa1 = *(const float4*)(Ag + a64 + k0);
      pb0 = *(const float4*)(Bg + (size_t)k0 * N);
      pb1 = *(const float4*)(Bg + (size_t)k0 * N + b8);
    }
    #pragma unroll
    for (int k = 0; k < 16; k++) {
      const float* ap = As + k * GLD + ty * 8;
      const float* bp = Bs + k * GLD + tx * 8;
      float4 a0 = *(const float4*)ap,       a1 = *(const float4*)(ap + 4);
      float4 b0 = *(const float4*)bp,       b1 = *(const float4*)(bp + 4);
      u64 bb[4] = { pk2(b0.x, b0.y), pk2(b0.z, b0.w),
                    pk2(b1.x, b1.y), pk2(b1.z, b1.w) };
      float ar[8] = { a0.x, a0.y, a0.z, a0.w, a1.x, a1.y, a1.z, a1.w };
      #pragma unroll
      for (int i = 0; i < 8; i++) {
        u64 ab = pk2(ar[i], ar[i]);
        fma2(acc[i][0], ab, bb[0]);
        fma2(acc[i][1], ab, bb[1]);
        fma2(acc[i][2], ab, bb[2]);
        fma2(acc[i][3], ab, bb[3]);
      }
    }
    if (more) {
      __syncthreads();
      As[(ak4 + 0) * GLD + arow] = pa0.x; As[(ak4 + 1) * GLD + arow] = pa0.y;
      As[(ak4 + 2) * GLD + arow] = pa0.z; As[(ak4 + 3) * GLD + arow] = pa0.w;
      As[(ak4 + 0) * GLD + arow + 64] = pa1.x; As[(ak4 + 1) * GLD + arow + 64] = pa1.y;
      As[(ak4 + 2) * GLD + arow + 64] = pa1.z; As[(ak4 + 3) * GLD + arow + 64] = pa1.w;
      *(float4*)(Bs + bkr * GLD + bn4) = pb0;
      *(float4*)(Bs + (bkr + 8) * GLD + bn4) = pb1;
      __syncthreads();
    }
  }

  int cb = col0 + tx * 8;
  float4 bi0 = *(const float4*)(bias + cb);
  float4 bi1 = *(const float4*)(bias + cb + 4);
  #pragma unroll
  for (int i = 0; i < 8; i++) {
    size_t r = row0 + ty * 8 + i;
    size_t off = r * N + cb;
    float2 c0 = up2(acc[i][0]), c1 = up2(acc[i][1]);
    float2 c2 = up2(acc[i][2]), c3 = up2(acc[i][3]);
    float o[8] = { c0.x + bi0.x, c0.y + bi0.y, c1.x + bi0.z, c1.y + bi0.w,
                   c2.x + bi1.x, c2.y + bi1.y, c3.x + bi1.z, c3.y + bi1.w };
    if (EPI == 1) {
      float4 r0 = *(const float4*)(res + off);
      float4 r1 = *(const float4*)(res + off + 4);
      o[0] += r0.x; o[1] += r0.y; o[2] += r0.z; o[3] += r0.w;
      o[4] += r1.x; o[5] += r1.y; o[6] += r1.z; o[7] += r1.w;
    }
    if (EPI == 2) {
      #pragma unroll
      for (int j = 0; j < 8; j++) o[j] = gelu_f(o[j]);
    }
    *(float4*)(C + off)     = make_float4(o[0], o[1], o[2], o[3]);
    *(float4*)(C + off + 4) = make_float4(o[4], o[5], o[6], o[7]);
  }
}

// ---------------- fused flash attention (FFMA2 inner products) ----------------
#define APAD 68
#define SMEM_ATTN (4 * 64 * APAD * 4)

__global__ __launch_bounds__(256) void attn_kernel(
    const float* __restrict__ Q, const float* __restrict__ Kk,
    const float* __restrict__ Vv, const float* __restrict__ Bt,
    float* __restrict__ ctx) {
  extern __shared__ float sm[];
  float* Qs = sm;
  float* Ks = sm + 64 * APAD;
  float* Vs = sm + 2 * 64 * APAD;
  float* Ps = sm + 3 * 64 * APAD;
  int bh = blockIdx.y;
  int b = bh >> 3, h = bh & 7;
  int t0 = blockIdx.x * 64;
  int tid = threadIdx.x;
  int ty = tid >> 4, tx = tid & 15;
  const size_t base = ((size_t)b * T_) * C_ + h * DH_;

  #pragma unroll
  for (int i = 0; i < 4; i++) {
    int lin = tid + i * 256;
    int row = lin >> 4, c4 = lin & 15;
    int t = t0 + row;
    float4 val = make_float4(0.f, 0.f, 0.f, 0.f);
    if (t < T_) val = *(const float4*)(Q + base + (size_t)t * C_ + c4 * 4);
    *(float4*)(Qs + row * APAD + c4 * 4) = val;
  }

  float m_[4], l_[4];
  u64 O2[4][2];
  #pragma unroll
  for (int i = 0; i < 4; i++) {
    m_[i] = -1e30f; l_[i] = 0.f;
    O2[i][0] = pk2(0.f, 0.f); O2[i][1] = pk2(0.f, 0.f);
  }

  for (int s0 = 0; s0 < T_; s0 += 64) {
    __syncthreads();
    #pragma unroll
    for (int i = 0; i < 4; i++) {
      int lin = tid + i * 256;
      int row = lin >> 4, c4 = lin & 15;
      int s = s0 + row;
      float4 kv = make_float4(0.f, 0.f, 0.f, 0.f), vv = kv;
      if (s < T_) {
        kv = *(const float4*)(Kk + base + (size_t)s * C_ + c4 * 4);
        vv = *(const float4*)(Vv + base + (size_t)s * C_ + c4 * 4);
      }
      *(float4*)(Ks + row * APAD + c4 * 4) = kv;
      *(float4*)(Vs + row * APAD + c4 * 4) = vv;
    }
    __syncthreads();

    // S = Q K^T via FFMA2: acc2[i][0]={S[tx],S[tx+16]}, acc2[i][1]={S[tx+32],S[tx+48]}
    u64 acc2[4][2] = {};
    #pragma unroll
    for (int d4 = 0; d4 < 16; d4++) {
      float a_[4][4], k_[4][4];
      #pragma unroll
      for (int i = 0; i < 4; i++)
        *(float4*)&a_[i][0] = *(const float4*)(Qs + (ty * 4 + i) * APAD + d4 * 4);
      #pragma unroll
      for (int j = 0; j < 4; j++)
        *(float4*)&k_[j][0] = *(const float4*)(Ks + (tx + 16 * j) * APAD + d4 * 4);
      #pragma unroll
      for (int c = 0; c < 4; c++) {
        u64 k01 = pk2(k_[0][c], k_[1][c]);
        u64 k23 = pk2(k_[2][c], k_[3][c]);
        #pragma unroll
        for (int i = 0; i < 4; i++) {
          u64 ab = pk2(a_[i][c], a_[i][c]);
          fma2(acc2[i][0], ab, k01);
          fma2(acc2[i][1], ab, k23);
        }
      }
    }

    // online softmax update
    #pragma unroll
    for (int i = 0; i < 4; i++) {
      int t = t0 + ty * 4 + i;
      int tcl = (t < T_) ? t : 0;
      const float* brow = Bt + ((size_t)h * T_ + tcl) * T_;
      float2 s01 = up2(acc2[i][0]);
      float2 s23 = up2(acc2[i][1]);
      float sraw[4] = { s01.x, s01.y, s23.x, s23.y };
      float sv[4];
      #pragma unroll
      for (int j = 0; j < 4; j++) {
        int s = s0 + tx + 16 * j;
        int scl = (s < T_) ? s : 0;
        bool ok = (t < T_) && (s < T_);
        sv[j] = ok ? fmaf(sraw[j], 0.125f, brow[scl]) : -1e30f;
      }
      float mc = fmaxf(fmaxf(sv[0], sv[1]), fmaxf(sv[2], sv[3]));
      #pragma unroll
      for (int o = 8; o; o >>= 1) mc = fmaxf(mc, __shfl_xor_sync(0xffffffffu, mc, o));
      float mn = fmaxf(m_[i], mc);
      float alpha = __expf(m_[i] - mn);
      float ls = 0.f;
      #pragma unroll
      for (int j = 0; j < 4; j++) { sv[j] = __expf(sv[j] - mn); ls += sv[j]; }
      #pragma unroll
      for (int o = 8; o; o >>= 1) ls += __shfl_xor_sync(0xffffffffu, ls, o);
      l_[i] = l_[i] * alpha + ls;
      m_[i] = mn;
      u64 al = pk2(alpha, alpha);
      mul2(O2[i][0], al); mul2(O2[i][1], al);
      #pragma unroll
      for (int j = 0; j < 4; j++) Ps[(ty * 4 + i) * APAD + tx + 16 * j] = sv[j];
    }
    __syncthreads();

    // O += P @ V via FFMA2 (O cols tx*4..+3)
    #pragma unroll
    for (int s4 = 0; s4 < 16; s4++) {
      float p_[4][4], v_[4][4];
      #pragma unroll
      for (int i = 0; i < 4; i++)
        *(float4*)&p_[i][0] = *(const float4*)(Ps + (ty * 4 + i) * APAD + s4 * 4);
      #pragma unroll
      for (int ss = 0; ss < 4; ss++)
        *(float4*)&v_[ss][0] = *(const float4*)(Vs + (s4 * 4 + ss) * APAD + tx * 4);
      #pragma unroll
      for (int ss = 0; ss < 4; ss++) {
        u64 v01 = pk2(v_[ss][0], v_[ss][1]);
        u64 v23 = pk2(v_[ss][2], v_[ss][3]);
        #pragma unroll
        for (int i = 0; i < 4; i++) {
          u64 ab = pk2(p_[i][ss], p_[i][ss]);
          fma2(O2[i][0], ab, v01);
          fma2(O2[i][1], ab, v23);
        }
      }
    }
  }

  #pragma unroll
  for (int i = 0; i < 4; i++) {
    int t = t0 + ty * 4 + i;
    if (t < T_) {
      float inv = 1.0f / l_[i];
      float2 lo = up2(O2[i][0]), hi = up2(O2[i][1]);
      float4 o = make_float4(lo.x * inv, lo.y * inv, hi.x * inv, hi.y * inv);
      *(float4*)(ctx + base + (size_t)t * C_ + tx * 4) = o;
    }
  }
}

// ---------------- launch ----------------
extern "C" void kernel_launch(void* const* d_in, const int* in_sizes, int n_in,
                              void* d_out, int out_size) {
  const float* x    = (const float*)d_in[0];
  const float* ln1s = (const float*)d_in[1];
  const float* ln1b = (const float*)d_in[2];
  const float* Wq   = (const float*)d_in[3];
  const float* bq   = (const float*)d_in[4];
  const float* Wk   = (const float*)d_in[5];
  const float* bk   = (const float*)d_in[6];
  const float* Wv   = (const float*)d_in[7];
  const float* bv   = (const float*)d_in[8];
  const float* Wo   = (const float*)d_in[9];
  const float* bo   = (const float*)d_in[10];
  const float* rpb  = (const float*)d_in[11];
  const float* ln2s = (const float*)d_in[12];
  const float* ln2b = (const float*)d_in[13];
  const float* W1   = (const float*)d_in[14];
  const float* b1   = (const float*)d_in[15];
  const float* W2   = (const float*)d_in[16];
  const float* b2   = (const float*)d_in[17];
  float* out = (float*)d_out;

  float *gY, *gQ, *gK, *gV, *gCTX, *gX1, *gHID, *gBIAS;
  cudaGetSymbolAddress((void**)&gY,    g_Y);
  cudaGetSymbolAddress((void**)&gQ,    g_Q);
  cudaGetSymbolAddress((void**)&gK,    g_K);
  cudaGetSymbolAddress((void**)&gV,    g_V);
  cudaGetSymbolAddress((void**)&gCTX,  g_CTX);
  cudaGetSymbolAddress((void**)&gX1,   g_X1);
  cudaGetSymbolAddress((void**)&gHID,  g_HID);
  cudaGetSymbolAddress((void**)&gBIAS, g_BIAS);

  cudaFuncSetAttribute((const void*)attn_kernel,
                       cudaFuncAttributeMaxDynamicSharedMemorySize, SMEM_ATTN);

  // 1. LN1
  ln_kernel<<<M_, 128>>>(x, ln1s, ln1b, gY);
  // 2. rel-pos bias table (independent)
  bias_expand<<<H_ * T_, 128>>>(rpb, gBIAS);
  // 3. Q, K, V projections
  dim3 g1(C_ / 128, M_ / 128);
  gemm_kernel<0><<<g1, 256>>>(gY, Wq, bq, nullptr, gQ, M_, C_, C_);
  gemm_kernel<0><<<g1, 256>>>(gY, Wk, bk, nullptr, gK, M_, C_, C_);
  gemm_kernel<0><<<g1, 256>>>(gY, Wv, bv, nullptr, gV, M_, C_, C_);
  // 4. fused attention -> ctx
  dim3 ga((T_ + 63) / 64, B_ * H_);
  attn_kernel<<<ga, 256, SMEM_ATTN>>>(gQ, gK, gV, gBIAS, gCTX);
  // 5. output projection + residual -> X1
  gemm_kernel<1><<<g1, 256>>>(gCTX, Wo, bo, x, gX1, M_, C_, C_);
  // 6. LN2
  ln_kernel<<<M_, 128>>>(gX1, ln2s, ln2b, gY);
  // 7. MLP up + gelu
  dim3 g2(MLP_ / 128, M_ / 128);
  gemm_kernel<2><<<g2, 256>>>(gY, W1, b1, nullptr, gHID, M_, MLP_, C_);
  // 8. MLP down + residual -> out
  gemm_kernel<1><<<g1, 256>>>(gHID, W2, b2, gX1, out, M_, C_, MLP_);
}

// round 5
// speedup vs baseline: 2.6660x; 2.0672x over previous
#include <cuda_runtime.h>
#include <cuda_bf16.h>
#include <cstdint>
#include <cstddef>

// ---------------- problem constants ----------------
#define B_   256
#define T_   361
#define C_   512
#define H_   8
#define DH_  64
#define MLP_ 2048
#define M_   (B_ * T_)          // 92416 = 722*128
#define SPAN_ 37
#define TABLE_ 1369

// ---------------- f32x2 packed-FMA helpers (attention) ----------------
typedef unsigned long long u64;
__device__ __forceinline__ u64 pk2(float a, float b) {
  u64 r; asm("mov.b64 %0,{%1,%2};" : "=l"(r) : "f"(a), "f"(b)); return r;
}
__device__ __forceinline__ void fma2(u64& d, u64 a, u64 b) {
  asm("fma.rn.f32x2 %0, %1, %2, %0;" : "+l"(d) : "l"(a), "l"(b));
}
__device__ __forceinline__ void mul2(u64& d, u64 a) {
  asm("mul.rn.f32x2 %0, %0, %1;" : "+l"(d) : "l"(a));
}
__device__ __forceinline__ float2 up2(u64 v) {
  float2 r; asm("mov.b64 {%0,%1},%2;" : "=f"(r.x), "=f"(r.y) : "l"(v)); return r;
}

// ---------------- baseline-PTX tensor-core helpers (no 'a' features) ----------------
__device__ __forceinline__ uint32_t smem_u32(const void* p) {
  uint32_t a;
  asm("{ .reg .u64 t; cvta.to.shared.u64 t, %1; cvt.u32.u64 %0, t; }" : "=r"(a) : "l"(p));
  return a;
}
__device__ __forceinline__ void cpa16(uint32_t s, const void* g) {
  asm volatile("cp.async.cg.shared.global [%0], [%1], 16;" :: "r"(s), "l"(g));
}
#define CP_COMMIT() asm volatile("cp.async.commit_group;" ::: "memory")
template<int Nw> __device__ __forceinline__ void cp_wait() {
  asm volatile("cp.async.wait_group %0;" :: "n"(Nw) : "memory");
}
__device__ __forceinline__ void ldsm4(uint32_t* r, uint32_t a) {
  asm volatile("ldmatrix.sync.aligned.m8n8.x4.shared.b16 {%0,%1,%2,%3}, [%4];"
               : "=r"(r[0]), "=r"(r[1]), "=r"(r[2]), "=r"(r[3]) : "r"(a));
}
__device__ __forceinline__ void mma16816(float* c, const uint32_t* a,
                                         uint32_t b0, uint32_t b1) {
  asm volatile(
      "mma.sync.aligned.m16n8k16.row.col.f32.bf16.bf16.f32 "
      "{%0,%1,%2,%3}, {%4,%5,%6,%7}, {%8,%9}, {%0,%1,%2,%3};"
      : "+f"(c[0]), "+f"(c[1]), "+f"(c[2]), "+f"(c[3])
      : "r"(a[0]), "r"(a[1]), "r"(a[2]), "r"(a[3]), "r"(b0), "r"(b1));
}

// ---------------- scratch (static device globals) ----------------
__device__ __nv_bfloat16 g_Yhi [(size_t)M_ * C_];
__device__ __nv_bfloat16 g_Ylo [(size_t)M_ * C_];
__device__ float         g_Q   [(size_t)M_ * C_];
__device__ float         g_K   [(size_t)M_ * C_];
__device__ float         g_V   [(size_t)M_ * C_];
__device__ __nv_bfloat16 g_CXhi[(size_t)M_ * C_];
__device__ __nv_bfloat16 g_CXlo[(size_t)M_ * C_];
__device__ float         g_X1  [(size_t)M_ * C_];
__device__ __nv_bfloat16 g_HIhi[(size_t)M_ * MLP_];
__device__ __nv_bfloat16 g_HIlo[(size_t)M_ * MLP_];
__device__ float         g_BIAS[(size_t)H_ * T_ * T_];
#define WOFF_Q  0
#define WOFF_K  (512 * 512)
#define WOFF_V  (2 * 512 * 512)
#define WOFF_O  (3 * 512 * 512)
#define WOFF_1  (4 * 512 * 512)
#define WOFF_2  (4 * 512 * 512 + 2048 * 512)
#define WTOT    (4 * 512 * 512 + 2 * 2048 * 512)
__device__ __nv_bfloat16 g_Whi[WTOT];
__device__ __nv_bfloat16 g_Wlo[WTOT];

// ---------------- helpers ----------------
__device__ __forceinline__ void split_bf(float v, __nv_bfloat16& h, __nv_bfloat16& l) {
  h = __float2bfloat16(v);
  l = __float2bfloat16(v - __bfloat162float(h));
}
__device__ __forceinline__ float gelu_f(float x) {
  float x3 = x * x * x;
  float t = tanhf(0.7978845608028654f * fmaf(0.044715f, x3, x));
  return 0.5f * x * (1.0f + t);
}

// ---------------- weight prep: W[K,N] fp32 -> hi/lo [N,K] bf16 ----------------
__global__ __launch_bounds__(256) void wprep(const float* __restrict__ W,
                                             __nv_bfloat16* __restrict__ hi,
                                             __nv_bfloat16* __restrict__ lo,
                                             int K, int N) {
  __shared__ float ts[32][33];
  int n0 = blockIdx.x * 32, k0 = blockIdx.y * 32;
  int tr = threadIdx.x >> 5, tc = threadIdx.x & 31;
  #pragma unroll
  for (int i = 0; i < 4; i++) {
    int r = tr + i * 8;
    ts[r][tc] = W[(size_t)(k0 + r) * N + n0 + tc];
  }
  __syncthreads();
  #pragma unroll
  for (int i = 0; i < 4; i++) {
    int r = tr + i * 8;                      // n-index within tile
    float v = ts[tc][r];
    __nv_bfloat16 h, l; split_bf(v, h, l);
    size_t off = (size_t)(n0 + r) * K + k0 + tc;
    hi[off] = h; lo[off] = l;
  }
}

// ---------------- LayerNorm -> hi/lo bf16 ----------------
__global__ __launch_bounds__(128) void ln_split(
    const float* __restrict__ x, const float* __restrict__ g,
    const float* __restrict__ b, __nv_bfloat16* __restrict__ yh,
    __nv_bfloat16* __restrict__ yl) {
  size_t row = blockIdx.x;
  const float4* xr = (const float4*)(x + row * C_);
  float4 v = xr[threadIdx.x];
  float s  = v.x + v.y + v.z + v.w;
  float s2 = fmaf(v.x, v.x, fmaf(v.y, v.y, fmaf(v.z, v.z, v.w * v.w)));
  #pragma unroll
  for (int o = 16; o; o >>= 1) {
    s  += __shfl_xor_sync(0xffffffffu, s, o);
    s2 += __shfl_xor_sync(0xffffffffu, s2, o);
  }
  __shared__ float sh[8];
  int w = threadIdx.x >> 5, ln = threadIdx.x & 31;
  if (ln == 0) { sh[w] = s; sh[4 + w] = s2; }
  __syncthreads();
  s  = sh[0] + sh[1] + sh[2] + sh[3];
  s2 = sh[4] + sh[5] + sh[6] + sh[7];
  float mu  = s * (1.0f / C_);
  float var = s2 * (1.0f / C_) - mu * mu;
  float rs  = rsqrtf(var + 1e-6f);
  float4 gg = ((const float4*)g)[threadIdx.x];
  float4 bb = ((const float4*)b)[threadIdx.x];
  float o[4];
  o[0] = (v.x - mu) * rs * gg.x + bb.x;
  o[1] = (v.y - mu) * rs * gg.y + bb.y;
  o[2] = (v.z - mu) * rs * gg.z + bb.z;
  o[3] = (v.w - mu) * rs * gg.w + bb.w;
  __nv_bfloat16 hh[4], ll[4];
  #pragma unroll
  for (int i = 0; i < 4; i++) split_bf(o[i], hh[i], ll[i]);
  size_t off = row * C_ + threadIdx.x * 4;
  *(uint2*)(yh + off) = *(uint2*)hh;
  *(uint2*)(yl + off) = *(uint2*)ll;
}

// ---------------- rel-pos bias expansion ----------------
__global__ void bias_expand(const float* __restrict__ rpb, float* __restrict__ bias) {
  int h = blockIdx.x / T_, t = blockIdx.x % T_;
  int tr = t / 19, tc = t % 19;
  const float* rh = rpb + h * TABLE_;
  float* br = bias + ((size_t)h * T_ + t) * T_;
  for (int s = threadIdx.x; s < T_; s += blockDim.x) {
    int sr = s / 19, sc = s % 19;
    br[s] = rh[(tr - sr + 18) * SPAN_ + (tc - sc + 18)];
  }
}

// ---------------- mma.sync GEMM (tensor pipe via fallback HMMA) ----------------
// D[M,N] = A[M,K] @ B[N,K]^T, 3-term bf16 compensation, fp32 accum.
// Block 128x128, 8 warps (4 M x 2 N), warp tile 32x64, BK=32, cp.async double buffer.
// smem per stage: Ahi(8K) Alo(8K) Bhi(8K) Blo(8K) = 32KB; 2 stages = 64KB.
// swizzle: 16B chunk c at row r stored at chunk (c ^ ((r>>1)&3)).
#define ST_SZ 32768
#define GMMA_SMEM (2 * ST_SZ)

template<int EPI>  // 0: +bias->Cf   1: +bias+res->Cf   2: gelu(+bias)->Chi/Clo
__global__ __launch_bounds__(256, 2) void gemm_mma(
    const __nv_bfloat16* __restrict__ Ahi, const __nv_bfloat16* __restrict__ Alo,
    const __nv_bfloat16* __restrict__ Bhi, const __nv_bfloat16* __restrict__ Blo,
    const float* __restrict__ bias, const float* __restrict__ res,
    float* __restrict__ Cf, __nv_bfloat16* __restrict__ Chi,
    __nv_bfloat16* __restrict__ Clo, int N, int K) {
  extern __shared__ char smc[];
  uint32_t sb = smem_u32(smc);
  int tid = threadIdx.x, lane = tid & 31, wid = tid >> 5;
  int wm = wid & 3, wn = wid >> 2;
  size_t row0 = (size_t)blockIdx.y * 128;
  int col0 = blockIdx.x * 128;
  const int nk = K >> 5;

  float acc[2][8][4];
  #pragma unroll
  for (int i = 0; i < 2; i++)
    #pragma unroll
    for (int j = 0; j < 8; j++)
      #pragma unroll
      for (int q = 0; q < 4; q++) acc[i][j][q] = 0.f;

  #define PREFETCH(kc, stg) do {                                               \
    const __nv_bfloat16* srcs_[4] = { Ahi, Alo, Bhi, Blo };                    \
    _Pragma("unroll")                                                          \
    for (int tl_ = 0; tl_ < 4; tl_++) {                                        \
      size_t rb_ = (tl_ < 2) ? row0 : (size_t)col0;                            \
      _Pragma("unroll")                                                        \
      for (int i_ = 0; i_ < 2; i_++) {                                         \
        int idx_ = tid + i_ * 256;                                             \
        int r_ = idx_ >> 2, c_ = idx_ & 3;                                     \
        uint32_t sa_ = sb + (stg) * ST_SZ + tl_ * 8192 + r_ * 64 +             \
                       ((c_ ^ ((r_ >> 1) & 3)) << 4);                          \
        const char* ga_ = (const char*)(srcs_[tl_] +                           \
                          (rb_ + r_) * (size_t)K + (kc) * 32) + c_ * 16;       \
        cpa16(sa_, ga_);                                                       \
      }                                                                        \
    }                                                                          \
    CP_COMMIT();                                                               \
  } while (0)

  PREFETCH(0, 0);

  for (int kc = 0; kc < nk; kc++) {
    int s = kc & 1;
    bool more = (kc + 1 < nk);
    if (more) PREFETCH(kc + 1, s ^ 1);
    if (more) cp_wait<1>(); else cp_wait<0>();
    __syncthreads();
    uint32_t tb = sb + s * ST_SZ;
    #pragma unroll
    for (int k16 = 0; k16 < 2; k16++) {
      int c0 = k16 * 2;
      uint32_t ah[2][4], al[2][4], bfr[4][4];
      #pragma unroll
      for (int fi = 0; fi < 2; fi++) {
        int lr = wm * 32 + fi * 16 + (lane & 15);
        int ch = c0 + (lane >> 4);
        uint32_t ad = tb + lr * 64 + ((ch ^ ((lr >> 1) & 3)) << 4);
        ldsm4(ah[fi], ad);
        ldsm4(al[fi], ad + 8192);
      }
      #pragma unroll
      for (int p = 0; p < 4; p++) {
        int nr = wn * 64 + p * 16 + ((lane >> 4) << 3) + (lane & 7);
        int ch = c0 + ((lane >> 3) & 1);
        uint32_t ad = tb + 16384 + nr * 64 + ((ch ^ ((nr >> 1) & 3)) << 4);
        ldsm4(bfr[p], ad);
      }
      #pragma unroll
      for (int fi = 0; fi < 2; fi++)
        #pragma unroll
        for (int j = 0; j < 8; j++)
          mma16816(acc[fi][j], ah[fi], bfr[j >> 1][(j & 1) * 2], bfr[j >> 1][(j & 1) * 2 + 1]);
      #pragma unroll
      for (int fi = 0; fi < 2; fi++)
        #pragma unroll
        for (int j = 0; j < 8; j++)
          mma16816(acc[fi][j], al[fi], bfr[j >> 1][(j & 1) * 2], bfr[j >> 1][(j & 1) * 2 + 1]);
      // overwrite B frags with Blo, third term
      #pragma unroll
      for (int p = 0; p < 4; p++) {
        int nr = wn * 64 + p * 16 + ((lane >> 4) << 3) + (lane & 7);
        int ch = c0 + ((lane >> 3) & 1);
        uint32_t ad = tb + 24576 + nr * 64 + ((ch ^ ((nr >> 1) & 3)) << 4);
        ldsm4(bfr[p], ad);
      }
      #pragma unroll
      for (int fi = 0; fi < 2; fi++)
        #pragma unroll
        for (int j = 0; j < 8; j++)
          mma16816(acc[fi][j], ah[fi], bfr[j >> 1][(j & 1) * 2], bfr[j >> 1][(j & 1) * 2 + 1]);
    }
    __syncthreads();
  }

  // ---- epilogue ----
  int rr = lane >> 2, ce = (lane & 3) * 2;
  #pragma unroll
  for (int fi = 0; fi < 2; fi++) {
    size_t gr0 = row0 + wm * 32 + fi * 16 + rr;
    #pragma unroll
    for (int j = 0; j < 8; j++) {
      int gc = col0 + wn * 64 + j * 8 + ce;
      float2 bv = *(const float2*)(bias + gc);
      float o0 = acc[fi][j][0] + bv.x, o1 = acc[fi][j][1] + bv.y;
      float o2 = acc[fi][j][2] + bv.x, o3 = acc[fi][j][3] + bv.y;
      size_t off0 = gr0 * (size_t)N + gc;
      size_t off1 = off0 + 8 * (size_t)N;
      if (EPI == 1) {
        float2 r0 = *(const float2*)(res + off0);
        float2 r1 = *(const float2*)(res + off1);
        o0 += r0.x; o1 += r0.y; o2 += r1.x; o3 += r1.y;
      }
      if (EPI == 2) {
        o0 = gelu_f(o0); o1 = gelu_f(o1); o2 = gelu_f(o2); o3 = gelu_f(o3);
        __nv_bfloat16 h0, l0, h1, l1;
        split_bf(o0, h0, l0); split_bf(o1, h1, l1);
        __nv_bfloat162 hp; hp.x = h0; hp.y = h1;
        __nv_bfloat162 lp; lp.x = l0; lp.y = l1;
        *(__nv_bfloat162*)(Chi + off0) = hp;
        *(__nv_bfloat162*)(Clo + off0) = lp;
        split_bf(o2, h0, l0); split_bf(o3, h1, l1);
        hp.x = h0; hp.y = h1; lp.x = l0; lp.y = l1;
        *(__nv_bfloat162*)(Chi + off1) = hp;
        *(__nv_bfloat162*)(Clo + off1) = lp;
      } else {
        *(float2*)(Cf + off0) = make_float2(o0, o1);
        *(float2*)(Cf + off1) = make_float2(o2, o3);
      }
    }
  }
}

// ---------------- fused flash attention (fp32 FFMA2), hi/lo output ----------------
#define APAD 68
#define SMEM_ATTN (4 * 64 * APAD * 4)

__global__ __launch_bounds__(256) void attn_kernel(
    const float* __restrict__ Q, const float* __restrict__ Kk,
    const float* __restrict__ Vv, const float* __restrict__ Bt,
    __nv_bfloat16* __restrict__ cxh, __nv_bfloat16* __restrict__ cxl) {
  extern __shared__ float sm[];
  float* Qs = sm;
  float* Ks = sm + 64 * APAD;
  float* Vs = sm + 2 * 64 * APAD;
  float* Ps = sm + 3 * 64 * APAD;
  int bh = blockIdx.y;
  int b = bh >> 3, h = bh & 7;
  int t0 = blockIdx.x * 64;
  int tid = threadIdx.x;
  int ty = tid >> 4, tx = tid & 15;
  const size_t base = ((size_t)b * T_) * C_ + h * DH_;

  #pragma unroll
  for (int i = 0; i < 4; i++) {
    int lin = tid + i * 256;
    int row = lin >> 4, c4 = lin & 15;
    int t = t0 + row;
    float4 val = make_float4(0.f, 0.f, 0.f, 0.f);
    if (t < T_) val = *(const float4*)(Q + base + (size_t)t * C_ + c4 * 4);
    *(float4*)(Qs + row * APAD + c4 * 4) = val;
  }

  float m_[4], l_[4];
  u64 O2[4][2];
  #pragma unroll
  for (int i = 0; i < 4; i++) {
    m_[i] = -1e30f; l_[i] = 0.f;
    O2[i][0] = pk2(0.f, 0.f); O2[i][1] = pk2(0.f, 0.f);
  }

  for (int s0 = 0; s0 < T_; s0 += 64) {
    __syncthreads();
    #pragma unroll
    for (int i = 0; i < 4; i++) {
      int lin = tid + i * 256;
      int row = lin >> 4, c4 = lin & 15;
      int s = s0 + row;
      float4 kv = make_float4(0.f, 0.f, 0.f, 0.f), vv = kv;
      if (s < T_) {
        kv = *(const float4*)(Kk + base + (size_t)s * C_ + c4 * 4);
        vv = *(const float4*)(Vv + base + (size_t)s * C_ + c4 * 4);
      }
      *(float4*)(Ks + row * APAD + c4 * 4) = kv;
      *(float4*)(Vs + row * APAD + c4 * 4) = vv;
    }
    __syncthreads();

    u64 acc2[4][2] = {};
    #pragma unroll
    for (int d4 = 0; d4 < 16; d4++) {
      float a_[4][4], k_[4][4];
      #pragma unroll
      for (int i = 0; i < 4; i++)
        *(float4*)&a_[i][0] = *(const float4*)(Qs + (ty * 4 + i) * APAD + d4 * 4);
      #pragma unroll
      for (int j = 0; j < 4; j++)
        *(float4*)&k_[j][0] = *(const float4*)(Ks + (tx + 16 * j) * APAD + d4 * 4);
      #pragma unroll
      for (int c = 0; c < 4; c++) {
        u64 k01 = pk2(k_[0][c], k_[1][c]);
        u64 k23 = pk2(k_[2][c], k_[3][c]);
        #pragma unroll
        for (int i = 0; i < 4; i++) {
          u64 ab = pk2(a_[i][c], a_[i][c]);
          fma2(acc2[i][0], ab, k01);
          fma2(acc2[i][1], ab, k23);
        }
      }
    }

    #pragma unroll
    for (int i = 0; i < 4; i++) {
      int t = t0 + ty * 4 + i;
      int tcl = (t < T_) ? t : 0;
      const float* brow = Bt + ((size_t)h * T_ + tcl) * T_;
      float2 s01 = up2(acc2[i][0]);
      float2 s23 = up2(acc2[i][1]);
      float sraw[4] = { s01.x, s01.y, s23.x, s23.y };
      float sv[4];
      #pragma unroll
      for (int j = 0; j < 4; j++) {
        int s = s0 + tx + 16 * j;
        int scl = (s < T_) ? s : 0;
        bool ok = (t < T_) && (s < T_);
        sv[j] = ok ? fmaf(sraw[j], 0.125f, brow[scl]) : -1e30f;
      }
      float mc = fmaxf(fmaxf(sv[0], sv[1]), fmaxf(sv[2], sv[3]));
      #pragma unroll
      for (int o = 8; o; o >>= 1) mc = fmaxf(mc, __shfl_xor_sync(0xffffffffu, mc, o));
      float mn = fmaxf(m_[i], mc);
      float alpha = __expf(m_[i] - mn);
      float ls = 0.f;
      #pragma unroll
      for (int j = 0; j < 4; j++) { sv[j] = __expf(sv[j] - mn); ls += sv[j]; }
      #pragma unroll
      for (int o = 8; o; o >>= 1) ls += __shfl_xor_sync(0xffffffffu, ls, o);
      l_[i] = l_[i] * alpha + ls;
      m_[i] = mn;
      u64 al = pk2(alpha, alpha);
      mul2(O2[i][0], al); mul2(O2[i][1], al);
      #pragma unroll
      for (int j = 0; j < 4; j++) Ps[(ty * 4 + i) * APAD + tx + 16 * j] = sv[j];
    }
    __syncthreads();

    #pragma unroll
    for (int s4 = 0; s4 < 16; s4++) {
      float p_[4][4], v_[4][4];
      #pragma unroll
      for (int i = 0; i < 4; i++)
        *(float4*)&p_[i][0] = *(const float4*)(Ps + (ty * 4 + i) * APAD + s4 * 4);
      #pragma unroll
      for (int ss = 0; ss < 4; ss++)
        *(float4*)&v_[ss][0] = *(const float4*)(Vs + (s4 * 4 + ss) * APAD + tx * 4);
      #pragma unroll
      for (int ss = 0; ss < 4; ss++) {
        u64 v01 = pk2(v_[ss][0], v_[ss][1]);
        u64 v23 = pk2(v_[ss][2], v_[ss][3]);
        #pragma unroll
        for (int i = 0; i < 4; i++) {
          u64 ab = pk2(p_[i][ss], p_[i][ss]);
          fma2(O2[i][0], ab, v01);
          fma2(O2[i][1], ab, v23);
        }
      }
    }
  }

  #pragma unroll
  for (int i = 0; i < 4; i++) {
    int t = t0 + ty * 4 + i;
    if (t < T_) {
      float inv = 1.0f / l_[i];
      float2 lo = up2(O2[i][0]), hi = up2(O2[i][1]);
      float o[4] = { lo.x * inv, lo.y * inv, hi.x * inv, hi.y * inv };
      __nv_bfloat16 hh[4], ll[4];
      #pragma unroll
      for (int j = 0; j < 4; j++) split_bf(o[j], hh[j], ll[j]);
      size_t off = base + (size_t)t * C_ + tx * 4;
      *(uint2*)(cxh + off) = *(uint2*)hh;
      *(uint2*)(cxl + off) = *(uint2*)ll;
    }
  }
}

// ---------------- launch ----------------
extern "C" void kernel_launch(void* const* d_in, const int* in_sizes, int n_in,
                              void* d_out, int out_size) {
  const float* x    = (const float*)d_in[0];
  const float* ln1s = (const float*)d_in[1];
  const float* ln1b = (const float*)d_in[2];
  const float* Wq   = (const float*)d_in[3];
  const float* bq   = (const float*)d_in[4];
  const float* Wk   = (const float*)d_in[5];
  const float* bk   = (const float*)d_in[6];
  const float* Wv   = (const float*)d_in[7];
  const float* bv   = (const float*)d_in[8];
  const float* Wo   = (const float*)d_in[9];
  const float* bo   = (const float*)d_in[10];
  const float* rpb  = (const float*)d_in[11];
  const float* ln2s = (const float*)d_in[12];
  const float* ln2b = (const float*)d_in[13];
  const float* W1   = (const float*)d_in[14];
  const float* b1   = (const float*)d_in[15];
  const float* W2   = (const float*)d_in[16];
  const float* b2   = (const float*)d_in[17];
  float* out = (float*)d_out;

  __nv_bfloat16 *yh, *yl, *cxh, *cxl, *hih, *hil, *wh, *wl;
  float *gQ, *gK, *gV, *gX1, *gBIAS;
  cudaGetSymbolAddress((void**)&yh,    g_Yhi);
  cudaGetSymbolAddress((void**)&yl,    g_Ylo);
  cudaGetSymbolAddress((void**)&gQ,    g_Q);
  cudaGetSymbolAddress((void**)&gK,    g_K);
  cudaGetSymbolAddress((void**)&gV,    g_V);
  cudaGetSymbolAddress((void**)&cxh,   g_CXhi);
  cudaGetSymbolAddress((void**)&cxl,   g_CXlo);
  cudaGetSymbolAddress((void**)&gX1,   g_X1);
  cudaGetSymbolAddress((void**)&hih,   g_HIhi);
  cudaGetSymbolAddress((void**)&hil,   g_HIlo);
  cudaGetSymbolAddress((void**)&gBIAS, g_BIAS);
  cudaGetSymbolAddress((void**)&wh,    g_Whi);
  cudaGetSymbolAddress((void**)&wl,    g_Wlo);

  cudaFuncSetAttribute((const void*)attn_kernel,
                       cudaFuncAttributeMaxDynamicSharedMemorySize, SMEM_ATTN);
  cudaFuncSetAttribute((const void*)gemm_mma<0>,
                       cudaFuncAttributeMaxDynamicSharedMemorySize, GMMA_SMEM);
  cudaFuncSetAttribute((const void*)gemm_mma<1>,
                       cudaFuncAttributeMaxDynamicSharedMemorySize, GMMA_SMEM);
  cudaFuncSetAttribute((const void*)gemm_mma<2>,
                       cudaFuncAttributeMaxDynamicSharedMemorySize, GMMA_SMEM);

  // weight prep (transpose + hi/lo split)
  wprep<<<dim3(16, 16), 256>>>(Wq, wh + WOFF_Q, wl + WOFF_Q, 512, 512);
  wprep<<<dim3(16, 16), 256>>>(Wk, wh + WOFF_K, wl + WOFF_K, 512, 512);
  wprep<<<dim3(16, 16), 256>>>(Wv, wh + WOFF_V, wl + WOFF_V, 512, 512);
  wprep<<<dim3(16, 16), 256>>>(Wo, wh + WOFF_O, wl + WOFF_O, 512, 512);
  wprep<<<dim3(64, 16), 256>>>(W1, wh + WOFF_1, wl + WOFF_1, 512, 2048);
  wprep<<<dim3(16, 64), 256>>>(W2, wh + WOFF_2, wl + WOFF_2, 2048, 512);

  // LN1 -> hi/lo ; bias table
  ln_split<<<M_, 128>>>(x, ln1s, ln1b, yh, yl);
  bias_expand<<<H_ * T_, 128>>>(rpb, gBIAS);

  // QKV projections (tensor pipe)
  dim3 g1(C_ / 128, M_ / 128);
  gemm_mma<0><<<g1, 256, GMMA_SMEM>>>(yh, yl, wh + WOFF_Q, wl + WOFF_Q, bq,
                                      nullptr, gQ, nullptr, nullptr, C_, C_);
  gemm_mma<0><<<g1, 256, GMMA_SMEM>>>(yh, yl, wh + WOFF_K, wl + WOFF_K, bk,
                                      nullptr, gK, nullptr, nullptr, C_, C_);
  gemm_mma<0><<<g1, 256, GMMA_SMEM>>>(yh, yl, wh + WOFF_V, wl + WOFF_V, bv,
                                      nullptr, gV, nullptr, nullptr, C_, C_);
  // attention
  dim3 ga((T_ + 63) / 64, B_ * H_);
  attn_kernel<<<ga, 256, SMEM_ATTN>>>(gQ, gK, gV, gBIAS, cxh, cxl);
  // output projection + residual
  gemm_mma<1><<<g1, 256, GMMA_SMEM>>>(cxh, cxl, wh + WOFF_O, wl + WOFF_O, bo,
                                      x, gX1, nullptr, nullptr, C_, C_);
  // LN2 -> hi/lo
  ln_split<<<M_, 128>>>(gX1, ln2s, ln2b, yh, yl);
  // MLP up + gelu -> hi/lo
  dim3 g2(MLP_ / 128, M_ / 128);
  gemm_mma<2><<<g2, 256, GMMA_SMEM>>>(yh, yl, wh + WOFF_1, wl + WOFF_1, b1,
                                      nullptr, nullptr, hih, hil, MLP_, C_);
  // MLP down + residual -> out
  gemm_mma<1><<<g1, 256, GMMA_SMEM>>>(hih, hil, wh + WOFF_2, wl + WOFF_2, b2,
                                      gX1, out, nullptr, nullptr, C_, MLP_);
}

// round 6
// speedup vs baseline: 3.4239x; 1.2843x over previous
#include <cuda_runtime.h>
#include <cuda_bf16.h>
#include <cstdint>
#include <cstddef>

// ---------------- problem constants ----------------
#define B_   256
#define T_   361
#define C_   512
#define H_   8
#define DH_  64
#define MLP_ 2048
#define M_   (B_ * T_)          // 92416 = 722*128
#define SPAN_ 37
#define TABLE_ 1369
#define BSTR_ 384               // padded bias row stride

// ---------------- PTX helpers (baseline features only) ----------------
__device__ __forceinline__ uint32_t smem_u32(const void* p) {
  uint32_t a;
  asm("{ .reg .u64 t; cvta.to.shared.u64 t, %1; cvt.u32.u64 %0, t; }" : "=r"(a) : "l"(p));
  return a;
}
__device__ __forceinline__ void cpa16(uint32_t s, const void* g) {
  asm volatile("cp.async.cg.shared.global [%0], [%1], 16;" :: "r"(s), "l"(g));
}
__device__ __forceinline__ void cpa16z(uint32_t s, const void* g, bool v) {
  int sz = v ? 16 : 0;
  asm volatile("cp.async.cg.shared.global [%0], [%1], 16, %2;" :: "r"(s), "l"(g), "r"(sz));
}
#define CP_COMMIT() asm volatile("cp.async.commit_group;" ::: "memory")
template<int Nw> __device__ __forceinline__ void cp_wait() {
  asm volatile("cp.async.wait_group %0;" :: "n"(Nw) : "memory");
}
__device__ __forceinline__ void ldsm4(uint32_t* r, uint32_t a) {
  asm volatile("ldmatrix.sync.aligned.m8n8.x4.shared.b16 {%0,%1,%2,%3}, [%4];"
               : "=r"(r[0]), "=r"(r[1]), "=r"(r[2]), "=r"(r[3]) : "r"(a));
}
__device__ __forceinline__ void ldsm4t(uint32_t* r, uint32_t a) {
  asm volatile("ldmatrix.sync.aligned.m8n8.x4.trans.shared.b16 {%0,%1,%2,%3}, [%4];"
               : "=r"(r[0]), "=r"(r[1]), "=r"(r[2]), "=r"(r[3]) : "r"(a));
}
__device__ __forceinline__ void mma16816(float* c, const uint32_t* a,
                                         uint32_t b0, uint32_t b1) {
  asm volatile(
      "mma.sync.aligned.m16n8k16.row.col.f32.bf16.bf16.f32 "
      "{%0,%1,%2,%3}, {%4,%5,%6,%7}, {%8,%9}, {%0,%1,%2,%3};"
      : "+f"(c[0]), "+f"(c[1]), "+f"(c[2]), "+f"(c[3])
      : "r"(a[0]), "r"(a[1]), "r"(a[2]), "r"(a[3]), "r"(b0), "r"(b1));
}

// ---------------- scratch (static device globals) ----------------
__device__ __nv_bfloat16 g_Yhi [(size_t)M_ * C_];
__device__ __nv_bfloat16 g_Ylo [(size_t)M_ * C_];
__device__ __nv_bfloat16 g_Qhi [(size_t)M_ * C_];
__device__ __nv_bfloat16 g_Qlo [(size_t)M_ * C_];
__device__ __nv_bfloat16 g_Khi [(size_t)M_ * C_];
__device__ __nv_bfloat16 g_Klo [(size_t)M_ * C_];
__device__ __nv_bfloat16 g_Vhi [(size_t)M_ * C_];
__device__ __nv_bfloat16 g_Vlo [(size_t)M_ * C_];
__device__ __nv_bfloat16 g_CXhi[(size_t)M_ * C_];
__device__ __nv_bfloat16 g_CXlo[(size_t)M_ * C_];
__device__ float         g_X1  [(size_t)M_ * C_];
__device__ __nv_bfloat16 g_HIhi[(size_t)M_ * MLP_];
__device__ __nv_bfloat16 g_HIlo[(size_t)M_ * MLP_];
__device__ float         g_BIAS[(size_t)H_ * T_ * BSTR_ + 16];
#define WOFF_Q  0
#define WOFF_K  (512 * 512)
#define WOFF_V  (2 * 512 * 512)
#define WOFF_O  (3 * 512 * 512)
#define WOFF_1  (4 * 512 * 512)
#define WOFF_2  (4 * 512 * 512 + 2048 * 512)
#define WTOT    (4 * 512 * 512 + 2 * 2048 * 512)
__device__ __nv_bfloat16 g_Whi[WTOT];
__device__ __nv_bfloat16 g_Wlo[WTOT];

// ---------------- helpers ----------------
__device__ __forceinline__ void split_bf(float v, __nv_bfloat16& h, __nv_bfloat16& l) {
  h = __float2bfloat16(v);
  l = __float2bfloat16(v - __bfloat162float(h));
}
__device__ __forceinline__ void pksplit(float p0, float p1, uint32_t& hi, uint32_t& lo) {
  __nv_bfloat162 h = __floats2bfloat162_rn(p0, p1);   // .x=p0 (low half)
  float r0 = p0 - __bfloat162float(h.x);
  float r1 = p1 - __bfloat162float(h.y);
  __nv_bfloat162 l = __floats2bfloat162_rn(r0, r1);
  hi = *(uint32_t*)&h; lo = *(uint32_t*)&l;
}
__device__ __forceinline__ float gelu_f(float x) {
  float x3 = x * x * x;
  float t = tanhf(0.7978845608028654f * fmaf(0.044715f, x3, x));
  return 0.5f * x * (1.0f + t);
}

// ---------------- weight prep: W[K,N] fp32 -> hi/lo [N,K] bf16 ----------------
__global__ __launch_bounds__(256) void wprep(const float* __restrict__ W,
                                             __nv_bfloat16* __restrict__ hi,
                                             __nv_bfloat16* __restrict__ lo,
                                             int K, int N) {
  __shared__ float ts[32][33];
  int n0 = blockIdx.x * 32, k0 = blockIdx.y * 32;
  int tr = threadIdx.x >> 5, tc = threadIdx.x & 31;
  #pragma unroll
  for (int i = 0; i < 4; i++) {
    int r = tr + i * 8;
    ts[r][tc] = W[(size_t)(k0 + r) * N + n0 + tc];
  }
  __syncthreads();
  #pragma unroll
  for (int i = 0; i < 4; i++) {
    int r = tr + i * 8;
    float v = ts[tc][r];
    __nv_bfloat16 h, l; split_bf(v, h, l);
    size_t off = (size_t)(n0 + r) * K + k0 + tc;
    hi[off] = h; lo[off] = l;
  }
}

// ---------------- LayerNorm -> hi/lo bf16 ----------------
__global__ __launch_bounds__(128) void ln_split(
    const float* __restrict__ x, const float* __restrict__ g,
    const float* __restrict__ b, __nv_bfloat16* __restrict__ yh,
    __nv_bfloat16* __restrict__ yl) {
  size_t row = blockIdx.x;
  const float4* xr = (const float4*)(x + row * C_);
  float4 v = xr[threadIdx.x];
  float s  = v.x + v.y + v.z + v.w;
  float s2 = fmaf(v.x, v.x, fmaf(v.y, v.y, fmaf(v.z, v.z, v.w * v.w)));
  #pragma unroll
  for (int o = 16; o; o >>= 1) {
    s  += __shfl_xor_sync(0xffffffffu, s, o);
    s2 += __shfl_xor_sync(0xffffffffu, s2, o);
  }
  __shared__ float sh[8];
  int w = threadIdx.x >> 5, ln = threadIdx.x & 31;
  if (ln == 0) { sh[w] = s; sh[4 + w] = s2; }
  __syncthreads();
  s  = sh[0] + sh[1] + sh[2] + sh[3];
  s2 = sh[4] + sh[5] + sh[6] + sh[7];
  float mu  = s * (1.0f / C_);
  float var = s2 * (1.0f / C_) - mu * mu;
  float rs  = rsqrtf(var + 1e-6f);
  float4 gg = ((const float4*)g)[threadIdx.x];
  float4 bb = ((const float4*)b)[threadIdx.x];
  float o[4];
  o[0] = (v.x - mu) * rs * gg.x + bb.x;
  o[1] = (v.y - mu) * rs * gg.y + bb.y;
  o[2] = (v.z - mu) * rs * gg.z + bb.z;
  o[3] = (v.w - mu) * rs * gg.w + bb.w;
  __nv_bfloat16 hh[4], ll[4];
  #pragma unroll
  for (int i = 0; i < 4; i++) split_bf(o[i], hh[i], ll[i]);
  size_t off = row * C_ + threadIdx.x * 4;
  *(uint2*)(yh + off) = *(uint2*)hh;
  *(uint2*)(yl + off) = *(uint2*)ll;
}

// ---------------- rel-pos bias expansion (padded stride 384) ----------------
__global__ void bias_expand(const float* __restrict__ rpb, float* __restrict__ bias) {
  int h = blockIdx.x / T_, t = blockIdx.x % T_;
  int tr = t / 19, tc = t % 19;
  const float* rh = rpb + h * TABLE_;
  float* br = bias + ((size_t)h * T_ + t) * BSTR_;
  for (int s = threadIdx.x; s < BSTR_; s += blockDim.x) {
    float v = 0.f;
    if (s < T_) {
      int sr = s / 19, sc = s % 19;
      v = rh[(tr - sr + 18) * SPAN_ + (tc - sc + 18)];
    }
    br[s] = v;
  }
}

// ---------------- mma.sync GEMM ----------------
// D[M,N] = A[M,K] @ B[N,K]^T, 3-term bf16 compensation, fp32 accum.
// EPI 0:+bias->Cf  1:+bias+res->Cf  2:gelu(+bias)->Chi/Clo  3:+bias->Chi/Clo
#define ST_SZ 32768
#define GMMA_SMEM (2 * ST_SZ)

template<int EPI>
__global__ __launch_bounds__(256, 2) void gemm_mma(
    const __nv_bfloat16* __restrict__ Ahi, const __nv_bfloat16* __restrict__ Alo,
    const __nv_bfloat16* __restrict__ Bhi, const __nv_bfloat16* __restrict__ Blo,
    const float* __restrict__ bias, const float* __restrict__ res,
    float* __restrict__ Cf, __nv_bfloat16* __restrict__ Chi,
    __nv_bfloat16* __restrict__ Clo, int N, int K) {
  extern __shared__ char smc[];
  uint32_t sb = smem_u32(smc);
  int tid = threadIdx.x, lane = tid & 31, wid = tid >> 5;
  int wm = wid & 3, wn = wid >> 2;
  size_t row0 = (size_t)blockIdx.y * 128;
  int col0 = blockIdx.x * 128;
  const int nk = K >> 5;

  float acc[2][8][4];
  #pragma unroll
  for (int i = 0; i < 2; i++)
    #pragma unroll
    for (int j = 0; j < 8; j++)
      #pragma unroll
      for (int q = 0; q < 4; q++) acc[i][j][q] = 0.f;

  #define PREFETCH(kc, stg) do {                                               \
    const __nv_bfloat16* srcs_[4] = { Ahi, Alo, Bhi, Blo };                    \
    _Pragma("unroll")                                                          \
    for (int tl_ = 0; tl_ < 4; tl_++) {                                        \
      size_t rb_ = (tl_ < 2) ? row0 : (size_t)col0;                            \
      _Pragma("unroll")                                                        \
      for (int i_ = 0; i_ < 2; i_++) {                                         \
        int idx_ = tid + i_ * 256;                                             \
        int r_ = idx_ >> 2, c_ = idx_ & 3;                                     \
        uint32_t sa_ = sb + (stg) * ST_SZ + tl_ * 8192 + r_ * 64 +             \
                       ((c_ ^ ((r_ >> 1) & 3)) << 4);                          \
        const char* ga_ = (const char*)(srcs_[tl_] +                           \
                          (rb_ + r_) * (size_t)K + (kc) * 32) + c_ * 16;       \
        cpa16(sa_, ga_);                                                       \
      }                                                                        \
    }                                                                          \
    CP_COMMIT();                                                               \
  } while (0)

  PREFETCH(0, 0);

  for (int kc = 0; kc < nk; kc++) {
    int s = kc & 1;
    bool more = (kc + 1 < nk);
    if (more) PREFETCH(kc + 1, s ^ 1);
    if (more) cp_wait<1>(); else cp_wait<0>();
    __syncthreads();
    uint32_t tb = sb + s * ST_SZ;
    #pragma unroll
    for (int k16 = 0; k16 < 2; k16++) {
      int c0 = k16 * 2;
      uint32_t ah[2][4], al[2][4], bfr[4][4];
      #pragma unroll
      for (int fi = 0; fi < 2; fi++) {
        int lr = wm * 32 + fi * 16 + (lane & 15);
        int ch = c0 + (lane >> 4);
        uint32_t ad = tb + lr * 64 + ((ch ^ ((lr >> 1) & 3)) << 4);
        ldsm4(ah[fi], ad);
        ldsm4(al[fi], ad + 8192);
      }
      #pragma unroll
      for (int p = 0; p < 4; p++) {
        int nr = wn * 64 + p * 16 + ((lane >> 4) << 3) + (lane & 7);
        int ch = c0 + ((lane >> 3) & 1);
        uint32_t ad = tb + 16384 + nr * 64 + ((ch ^ ((nr >> 1) & 3)) << 4);
        ldsm4(bfr[p], ad);
      }
      #pragma unroll
      for (int fi = 0; fi < 2; fi++)
        #pragma unroll
        for (int j = 0; j < 8; j++)
          mma16816(acc[fi][j], ah[fi], bfr[j >> 1][(j & 1) * 2], bfr[j >> 1][(j & 1) * 2 + 1]);
      #pragma unroll
      for (int fi = 0; fi < 2; fi++)
        #pragma unroll
        for (int j = 0; j < 8; j++)
          mma16816(acc[fi][j], al[fi], bfr[j >> 1][(j & 1) * 2], bfr[j >> 1][(j & 1) * 2 + 1]);
      #pragma unroll
      for (int p = 0; p < 4; p++) {
        int nr = wn * 64 + p * 16 + ((lane >> 4) << 3) + (lane & 7);
        int ch = c0 + ((lane >> 3) & 1);
        uint32_t ad = tb + 24576 + nr * 64 + ((ch ^ ((nr >> 1) & 3)) << 4);
        ldsm4(bfr[p], ad);
      }
      #pragma unroll
      for (int fi = 0; fi < 2; fi++)
        #pragma unroll
        for (int j = 0; j < 8; j++)
          mma16816(acc[fi][j], ah[fi], bfr[j >> 1][(j & 1) * 2], bfr[j >> 1][(j & 1) * 2 + 1]);
    }
    __syncthreads();
  }

  // ---- epilogue ----
  int rr = lane >> 2, ce = (lane & 3) * 2;
  #pragma unroll
  for (int fi = 0; fi < 2; fi++) {
    size_t gr0 = row0 + wm * 32 + fi * 16 + rr;
    #pragma unroll
    for (int j = 0; j < 8; j++) {
      int gc = col0 + wn * 64 + j * 8 + ce;
      float2 bv = *(const float2*)(bias + gc);
      float o0 = acc[fi][j][0] + bv.x, o1 = acc[fi][j][1] + bv.y;
      float o2 = acc[fi][j][2] + bv.x, o3 = acc[fi][j][3] + bv.y;
      size_t off0 = gr0 * (size_t)N + gc;
      size_t off1 = off0 + 8 * (size_t)N;
      if (EPI == 1) {
        float2 r0 = *(const float2*)(res + off0);
        float2 r1 = *(const float2*)(res + off1);
        o0 += r0.x; o1 += r0.y; o2 += r1.x; o3 += r1.y;
      }
      if (EPI >= 2) {
        if (EPI == 2) { o0 = gelu_f(o0); o1 = gelu_f(o1); o2 = gelu_f(o2); o3 = gelu_f(o3); }
        uint32_t h01, l01, h23, l23;
        pksplit(o0, o1, h01, l01);
        pksplit(o2, o3, h23, l23);
        *(uint32_t*)(Chi + off0) = h01;
        *(uint32_t*)(Clo + off0) = l01;
        *(uint32_t*)(Chi + off1) = h23;
        *(uint32_t*)(Clo + off1) = l23;
      } else {
        *(float2*)(Cf + off0) = make_float2(o0, o1);
        *(float2*)(Cf + off1) = make_float2(o2, o3);
      }
    }
  }
}

// ---------------- tensor-core flash attention (no-max softmax) ----------------
// Block: 128 q-rows x (b,h). 8 warps: wm=wid&3 (32 q rows), wn=wid>>2 (32 s cols).
// Loop 6 chunks of 64 s. S = QK^T 3-term bf16; P=exp(S/8+bias); O += P@V 3-term.
#define AT_Q_OFF   0          // Qhi 16KB, Qlo 16KB
#define AT_STG_OFF 32768      // 2 stages x (Khi,Klo,Vhi,Vlo = 32KB)
#define AT_STG_SZ  32768
#define AT_OSM_OFF 32768      // epilogue reuse: O[128][66] fp32 = 33792B
#define AT_LRED_OFF 98304     // 128*2 floats
#define AT_LINV_OFF 99328     // 128 floats
#define AT_SMEM    99904

__global__ __launch_bounds__(256, 1) void attn_mma(
    const __nv_bfloat16* __restrict__ Qh, const __nv_bfloat16* __restrict__ Ql,
    const __nv_bfloat16* __restrict__ Kh, const __nv_bfloat16* __restrict__ Kl,
    const __nv_bfloat16* __restrict__ Vh, const __nv_bfloat16* __restrict__ Vl,
    const float* __restrict__ Bt,
    __nv_bfloat16* __restrict__ cxh, __nv_bfloat16* __restrict__ cxl) {
  extern __shared__ char smc[];
  uint32_t sb = smem_u32(smc);
  int tid = threadIdx.x, lane = tid & 31, wid = tid >> 5;
  int wm = wid & 3, wn = wid >> 2;
  int bh = blockIdx.y, b = bh >> 3, h = bh & 7;
  int t0 = blockIdx.x * 128;
  const size_t gbase = (size_t)b * T_ * C_ + h * DH_;

  // Q tiles (hi/lo), swizzled: chunk c at row r -> c ^ (r&7)
  #pragma unroll
  for (int i = 0; i < 4; i++) {
    int idx = tid + i * 256;            // 1024 chunks
    int r = idx >> 3, c = idx & 7;
    int t = t0 + r;
    bool v = t < T_;
    uint32_t sa = sb + AT_Q_OFF + r * 128 + ((c ^ (r & 7)) << 4);
    cpa16z(sa,         (const char*)(Qh + gbase + (size_t)t * C_ + c * 8), v);
    cpa16z(sa + 16384, (const char*)(Ql + gbase + (size_t)t * C_ + c * 8), v);
  }

  #define PREF_KV(sc_, stg_) do {                                              \
    const __nv_bfloat16* srcs_[4] = { Kh, Kl, Vh, Vl };                        \
    _Pragma("unroll")                                                          \
    for (int tl_ = 0; tl_ < 4; tl_++) {                                        \
      _Pragma("unroll")                                                        \
      for (int i_ = 0; i_ < 2; i_++) {                                         \
        int idx_ = tid + i_ * 256;                                             \
        int r_ = idx_ >> 3, c_ = idx_ & 7;                                     \
        int s_ = (sc_) * 64 + r_;                                              \
        uint32_t sa_ = sb + AT_STG_OFF + (stg_) * AT_STG_SZ + tl_ * 8192 +     \
                       r_ * 128 + ((c_ ^ (r_ & 7)) << 4);                      \
        cpa16z(sa_, (const char*)(srcs_[tl_] + gbase + (size_t)s_ * C_ + c_ * 8), \
               s_ < T_);                                                       \
      }                                                                        \
    }                                                                          \
  } while (0)

  PREF_KV(0, 0);
  CP_COMMIT();

  float oacc[2][8][4];
  #pragma unroll
  for (int i = 0; i < 2; i++)
    #pragma unroll
    for (int j = 0; j < 8; j++)
      #pragma unroll
      for (int q = 0; q < 4; q++) oacc[i][j][q] = 0.f;
  float lsum[2][2] = {{0.f, 0.f}, {0.f, 0.f}};

  for (int sc = 0; sc < 6; sc++) {
    int s0 = sc * 64;
    if (sc < 5) { PREF_KV(sc + 1, (sc + 1) & 1); CP_COMMIT(); cp_wait<1>(); }
    else cp_wait<0>();
    __syncthreads();
    uint32_t stg = sb + AT_STG_OFF + (sc & 1) * AT_STG_SZ;

    // bias fragments (prefetch early; L2-resident table)
    float2 bfrag[2][4][2];
    {
      int rb0 = t0 + wm * 32 + (lane >> 2);
      #pragma unroll
      for (int fi = 0; fi < 2; fi++) {
        int ra = rb0 + fi * 16, rb = rb0 + fi * 16 + 8;
        int rca = (ra < T_) ? ra : 0;
        int rcb = (rb < T_) ? rb : 0;
        const float* bra = Bt + ((size_t)h * T_ + rca) * BSTR_;
        const float* brb = Bt + ((size_t)h * T_ + rcb) * BSTR_;
        #pragma unroll
        for (int j = 0; j < 4; j++) {
          int cb = s0 + wn * 32 + j * 8 + (lane & 3) * 2;
          bfrag[fi][j][0] = *(const float2*)(bra + cb);
          bfrag[fi][j][1] = *(const float2*)(brb + cb);
        }
      }
    }

    // ---- S = Q K^T (3-term) ----
    float sacc[2][4][4];
    #pragma unroll
    for (int i = 0; i < 2; i++)
      #pragma unroll
      for (int j = 0; j < 4; j++)
        #pragma unroll
        for (int q = 0; q < 4; q++) sacc[i][j][q] = 0.f;

    #pragma unroll
    for (int d16 = 0; d16 < 4; d16++) {
      uint32_t qh_[2][4], ql_[2][4], kh_[2][4], kl_[2][4];
      #pragma unroll
      for (int fi = 0; fi < 2; fi++) {
        int lr = wm * 32 + fi * 16 + (lane & 15);
        int ch = d16 * 2 + (lane >> 4);
        uint32_t ad = sb + AT_Q_OFF + lr * 128 + ((ch ^ (lr & 7)) << 4);
        ldsm4(qh_[fi], ad);
        ldsm4(ql_[fi], ad + 16384);
      }
      #pragma unroll
      for (int p = 0; p < 2; p++) {
        int sr = wn * 32 + p * 16 + ((lane >> 4) << 3) + (lane & 7);
        int ch = d16 * 2 + ((lane >> 3) & 1);
        uint32_t ad = stg + sr * 128 + ((ch ^ (sr & 7)) << 4);
        ldsm4(kh_[p], ad);
        ldsm4(kl_[p], ad + 8192);
      }
      #pragma unroll
      for (int fi = 0; fi < 2; fi++)
        #pragma unroll
        for (int j = 0; j < 4; j++) {
          int p = j >> 1, hf = (j & 1) * 2;
          mma16816(sacc[fi][j], qh_[fi], kh_[p][hf], kh_[p][hf + 1]);
          mma16816(sacc[fi][j], qh_[fi], kl_[p][hf], kl_[p][hf + 1]);
          mma16816(sacc[fi][j], ql_[fi], kh_[p][hf], kh_[p][hf + 1]);
        }
    }

    // ---- softmax (exp, no max) + pack P into A-fragments ----
    uint32_t pah[2][2][4], pal[2][2][4];
    #pragma unroll
    for (int fi = 0; fi < 2; fi++) {
      #pragma unroll
      for (int j = 0; j < 4; j++) {
        int cb = s0 + wn * 32 + j * 8 + (lane & 3) * 2;
        bool v0 = cb < T_, v1 = (cb + 1) < T_;
        float p0 = v0 ? __expf(fmaf(sacc[fi][j][0], 0.125f, bfrag[fi][j][0].x)) : 0.f;
        float p1 = v1 ? __expf(fmaf(sacc[fi][j][1], 0.125f, bfrag[fi][j][0].y)) : 0.f;
        float p2 = v0 ? __expf(fmaf(sacc[fi][j][2], 0.125f, bfrag[fi][j][1].x)) : 0.f;
        float p3 = v1 ? __expf(fmaf(sacc[fi][j][3], 0.125f, bfrag[fi][j][1].y)) : 0.f;
        lsum[fi][0] += p0 + p1;
        lsum[fi][1] += p2 + p3;
        int kk = j >> 1, sl = (j & 1) * 2;
        pksplit(p0, p1, pah[fi][kk][sl],     pal[fi][kk][sl]);
        pksplit(p2, p3, pah[fi][kk][sl + 1], pal[fi][kk][sl + 1]);
      }
    }

    // ---- O += P V (3-term), V via ldmatrix.trans ----
    #pragma unroll
    for (int kk = 0; kk < 2; kk++) {
      uint32_t vh_[4][4], vl_[4][4];
      #pragma unroll
      for (int dg = 0; dg < 4; dg++) {
        int sr = wn * 32 + kk * 16 + ((lane >> 3) & 1) * 8 + (lane & 7);
        int ch = dg * 2 + (lane >> 4);
        uint32_t ad = stg + 16384 + sr * 128 + ((ch ^ (sr & 7)) << 4);
        ldsm4t(vh_[dg], ad);
        ldsm4t(vl_[dg], ad + 8192);
      }
      #pragma unroll
      for (int fi = 0; fi < 2; fi++)
        #pragma unroll
        for (int n = 0; n < 8; n++) {
          int dg = n >> 1, hf = (n & 1) * 2;
          mma16816(oacc[fi][n], pah[fi][kk], vh_[dg][hf], vh_[dg][hf + 1]);
          mma16816(oacc[fi][n], pah[fi][kk], vl_[dg][hf], vl_[dg][hf + 1]);
          mma16816(oacc[fi][n], pal[fi][kk], vh_[dg][hf], vh_[dg][hf + 1]);
        }
    }
    __syncthreads();
  }

  // ---- epilogue: reduce l across lanes+warps, sum O partials, normalize ----
  #pragma unroll
  for (int fi = 0; fi < 2; fi++)
    #pragma unroll
    for (int hh = 0; hh < 2; hh++) {
      float v = lsum[fi][hh];
      v += __shfl_xor_sync(0xffffffffu, v, 1);
      v += __shfl_xor_sync(0xffffffffu, v, 2);
      lsum[fi][hh] = v;
    }
  float* lred = (float*)(smc + AT_LRED_OFF);
  float* linv = (float*)(smc + AT_LINV_OFF);
  float* osm  = (float*)(smc + AT_OSM_OFF);
  if ((lane & 3) == 0) {
    #pragma unroll
    for (int fi = 0; fi < 2; fi++)
      #pragma unroll
      for (int hh = 0; hh < 2; hh++) {
        int r = wm * 32 + fi * 16 + (lane >> 2) + hh * 8;
        lred[r * 2 + wn] = lsum[fi][hh];
      }
  }
  __syncthreads();
  if (tid < 128) linv[tid] = 1.0f / (lred[tid * 2] + lred[tid * 2 + 1]);
  if (wn == 0) {
    #pragma unroll
    for (int fi = 0; fi < 2; fi++) {
      int r0 = wm * 32 + fi * 16 + (lane >> 2);
      #pragma unroll
      for (int n = 0; n < 8; n++) {
        int c = n * 8 + (lane & 3) * 2;
        osm[r0 * 66 + c]       = oacc[fi][n][0];
        osm[r0 * 66 + c + 1]   = oacc[fi][n][1];
        osm[(r0 + 8) * 66 + c]     = oacc[fi][n][2];
        osm[(r0 + 8) * 66 + c + 1] = oacc[fi][n][3];
      }
    }
  }
  __syncthreads();
  if (wn == 1) {
    #pragma unroll
    for (int fi = 0; fi < 2; fi++) {
      int r0 = wm * 32 + fi * 16 + (lane >> 2);
      #pragma unroll
      for (int n = 0; n < 8; n++) {
        int c = n * 8 + (lane & 3) * 2;
        osm[r0 * 66 + c]       += oacc[fi][n][0];
        osm[r0 * 66 + c + 1]   += oacc[fi][n][1];
        osm[(r0 + 8) * 66 + c]     += oacc[fi][n][2];
        osm[(r0 + 8) * 66 + c + 1] += oacc[fi][n][3];
      }
    }
  }
  __syncthreads();
  #pragma unroll
  for (int i = 0; i < 8; i++) {
    int u = tid + i * 256;              // 2048 float4-units
    int r = u >> 4, c4 = (u & 15) * 4;
    int t = t0 + r;
    if (t < T_) {
      float iv = linv[r];
      float f0 = osm[r * 66 + c4]     * iv;
      float f1 = osm[r * 66 + c4 + 1] * iv;
      float f2 = osm[r * 66 + c4 + 2] * iv;
      float f3 = osm[r * 66 + c4 + 3] * iv;
      uint32_t h01, l01, h23, l23;
      pksplit(f0, f1, h01, l01);
      pksplit(f2, f3, h23, l23);
      size_t off = gbase + (size_t)t * C_ + c4;
      *(uint2*)(cxh + off) = make_uint2(h01, h23);
      *(uint2*)(cxl + off) = make_uint2(l01, l23);
    }
  }
}

// ---------------- launch ----------------
extern "C" void kernel_launch(void* const* d_in, const int* in_sizes, int n_in,
                              void* d_out, int out_size) {
  const float* x    = (const float*)d_in[0];
  const float* ln1s = (const float*)d_in[1];
  const float* ln1b = (const float*)d_in[2];
  const float* Wq   = (const float*)d_in[3];
  const float* bq   = (const float*)d_in[4];
  const float* Wk   = (const float*)d_in[5];
  const float* bk   = (const float*)d_in[6];
  const float* Wv   = (const float*)d_in[7];
  const float* bv   = (const float*)d_in[8];
  const float* Wo   = (const float*)d_in[9];
  const float* bo   = (const float*)d_in[10];
  const float* rpb  = (const float*)d_in[11];
  const float* ln2s = (const float*)d_in[12];
  const float* ln2b = (const float*)d_in[13];
  const float* W1   = (const float*)d_in[14];
  const float* b1   = (const float*)d_in[15];
  const float* W2   = (const float*)d_in[16];
  const float* b2   = (const float*)d_in[17];
  float* out = (float*)d_out;

  __nv_bfloat16 *yh, *yl, *qh, *ql, *kh, *kl, *vh, *vl, *cxh, *cxl, *hih, *hil, *wh, *wl;
  float *gX1, *gBIAS;
  cudaGetSymbolAddress((void**)&yh,    g_Yhi);
  cudaGetSymbolAddress((void**)&yl,    g_Ylo);
  cudaGetSymbolAddress((void**)&qh,    g_Qhi);
  cudaGetSymbolAddress((void**)&ql,    g_Qlo);
  cudaGetSymbolAddress((void**)&kh,    g_Khi);
  cudaGetSymbolAddress((void**)&kl,    g_Klo);
  cudaGetSymbolAddress((void**)&vh,    g_Vhi);
  cudaGetSymbolAddress((void**)&vl,    g_Vlo);
  cudaGetSymbolAddress((void**)&cxh,   g_CXhi);
  cudaGetSymbolAddress((void**)&cxl,   g_CXlo);
  cudaGetSymbolAddress((void**)&gX1,   g_X1);
  cudaGetSymbolAddress((void**)&hih,   g_HIhi);
  cudaGetSymbolAddress((void**)&hil,   g_HIlo);
  cudaGetSymbolAddress((void**)&gBIAS, g_BIAS);
  cudaGetSymbolAddress((void**)&wh,    g_Whi);
  cudaGetSymbolAddress((void**)&wl,    g_Wlo);

  cudaFuncSetAttribute((const void*)attn_mma,
                       cudaFuncAttributeMaxDynamicSharedMemorySize, AT_SMEM);
  cudaFuncSetAttribute((const void*)gemm_mma<0>,
                       cudaFuncAttributeMaxDynamicSharedMemorySize, GMMA_SMEM);
  cudaFuncSetAttribute((const void*)gemm_mma<1>,
                       cudaFuncAttributeMaxDynamicSharedMemorySize, GMMA_SMEM);
  cudaFuncSetAttribute((const void*)gemm_mma<2>,
                       cudaFuncAttributeMaxDynamicSharedMemorySize, GMMA_SMEM);
  cudaFuncSetAttribute((const void*)gemm_mma<3>,
                       cudaFuncAttributeMaxDynamicSharedMemorySize, GMMA_SMEM);

  // weight prep (transpose + hi/lo split)
  wprep<<<dim3(16, 16), 256>>>(Wq, wh + WOFF_Q, wl + WOFF_Q, 512, 512);
  wprep<<<dim3(16, 16), 256>>>(Wk, wh + WOFF_K, wl + WOFF_K, 512, 512);
  wprep<<<dim3(16, 16), 256>>>(Wv, wh + WOFF_V, wl + WOFF_V, 512, 512);
  wprep<<<dim3(16, 16), 256>>>(Wo, wh + WOFF_O, wl + WOFF_O, 512, 512);
  wprep<<<dim3(64, 16), 256>>>(W1, wh + WOFF_1, wl + WOFF_1, 512, 2048);
  wprep<<<dim3(16, 64), 256>>>(W2, wh + WOFF_2, wl + WOFF_2, 2048, 512);

  // LN1 -> hi/lo ; bias table
  ln_split<<<M_, 128>>>(x, ln1s, ln1b, yh, yl);
  bias_expand<<<H_ * T_, 128>>>(rpb, gBIAS);

  // QKV projections -> hi/lo bf16 (tensor pipe)
  dim3 g1(C_ / 128, M_ / 128);
  gemm_mma<3><<<g1, 256, GMMA_SMEM>>>(yh, yl, wh + WOFF_Q, wl + WOFF_Q, bq,
                                      nullptr, nullptr, qh, ql, C_, C_);
  gemm_mma<3><<<g1, 256, GMMA_SMEM>>>(yh, yl, wh + WOFF_K, wl + WOFF_K, bk,
                                      nullptr, nullptr, kh, kl, C_, C_);
  gemm_mma<3><<<g1, 256, GMMA_SMEM>>>(yh, yl, wh + WOFF_V, wl + WOFF_V, bv,
                                      nullptr, nullptr, vh, vl, C_, C_);
  // attention (tensor pipe)
  dim3 ga(3, B_ * H_);
  attn_mma<<<ga, 256, AT_SMEM>>>(qh, ql, kh, kl, vh, vl, gBIAS, cxh, cxl);
  // output projection + residual
  gemm_mma<1><<<g1, 256, GMMA_SMEM>>>(cxh, cxl, wh + WOFF_O, wl + WOFF_O, bo,
                                      x, gX1, nullptr, nullptr, C_, C_);
  // LN2 -> hi/lo
  ln_split<<<M_, 128>>>(gX1, ln2s, ln2b, yh, yl);
  // MLP up + gelu -> hi/lo
  dim3 g2(MLP_ / 128, M_ / 128);
  gemm_mma<2><<<g2, 256, GMMA_SMEM>>>(yh, yl, wh + WOFF_1, wl + WOFF_1, b1,
                                      nullptr, nullptr, hih, hil, MLP_, C_);
  // MLP down + residual -> out
  gemm_mma<1><<<g1, 256, GMMA_SMEM>>>(hih, hil, wh + WOFF_2, wl + WOFF_2, b2,
                                      gX1, out, nullptr, nullptr, C_, MLP_);
}